// round 13
// baseline (speedup 1.0000x reference)
#include <cuda_runtime.h>
#include <cuda_fp16.h>
#include <math.h>
#include <stdint.h>

typedef unsigned long long u64;

// ---------------- scratch (device globals; no allocation allowed) ----------
__device__ float g_xg  [16u*2048u*512u];   // precomputed input gates [B,S,4H]
__device__ float g_lstm[16u*2048u*128u];   // lstm hidden states [B,S,H]
__device__ float g_ctx [16u*2048u*128u];   // attention context [B,S,H]
__device__ float g_ha  [32768u*132u];      // MLP ping buffer (stride 132)
__device__ float g_hb  [32768u*132u];      // MLP pong buffer

__device__ __forceinline__ float sigf(float x) {
    return __fdividef(1.f, 1.f + __expf(-x));
}
__device__ __forceinline__ float tanh_fast(float x) {
    return fmaf(2.f, sigf(2.f * x), -1.f);
}

// packed f32x2 helpers ------------------------------------------------------
__device__ __forceinline__ void fma2(u64& c, u64 a, u64 b) {
    asm("fma.rn.f32x2 %0, %1, %2, %0;" : "+l"(c) : "l"(a), "l"(b));
}
__device__ __forceinline__ u64 pk(float x, float y) {
    u64 r;
    asm("mov.b64 %0, {%1, %2};" : "=l"(r)
        : "r"(__float_as_uint(x)), "r"(__float_as_uint(y)));
    return r;
}
__device__ __forceinline__ float2 upk(u64 v) {
    unsigned lo, hi;
    asm("mov.b64 {%0, %1}, %2;" : "=r"(lo), "=r"(hi) : "l"(v));
    return make_float2(__uint_as_float(lo), __uint_as_float(hi));
}
__device__ __forceinline__ float hsum2(u64 v) { float2 f = upk(v); return f.x + f.y; }
__device__ __forceinline__ u64 h2f2(unsigned h2bits) {   // half2 -> packed f32x2
    __half2 h = *(__half2*)&h2bits;
    float2 f = __half22float2(h);
    return pk(f.x, f.y);
}
__device__ __forceinline__ unsigned f2h2(float x, float y) {
    __half2 h = __floats2half2_rn(x, y);
    return *(unsigned*)&h;
}

// tf32 helpers ---------------------------------------------------------------
__device__ __forceinline__ unsigned tf32of(float f) {
    unsigned u; asm("cvt.rna.tf32.f32 %0, %1;" : "=r"(u) : "f"(f)); return u;
}
__device__ __forceinline__ void mma_tf32(float* c, const unsigned* a,
                                         unsigned b0, unsigned b1) {
    asm volatile(
        "mma.sync.aligned.m16n8k8.row.col.f32.tf32.tf32.f32 "
        "{%0,%1,%2,%3}, {%4,%5,%6,%7}, {%8,%9}, {%0,%1,%2,%3};"
        : "+f"(c[0]), "+f"(c[1]), "+f"(c[2]), "+f"(c[3])
        : "r"(a[0]), "r"(a[1]), "r"(a[2]), "r"(a[3]), "r"(b0), "r"(b1));
}

// column permutation: (c, c+4) within each 8-group become adjacent
__device__ __forceinline__ int permc(int c) {
    return (c & ~7) | ((c & 3) << 1) | ((c >> 2) & 1);
}

__global__ void k_nop() {}

// ---------------- K1: xg = x @ W_ih^T + b_ih — PROVEN f32x2 (R4) ----------
__global__ void k_xg(const float* __restrict__ x,
                     const float* __restrict__ Wih,
                     const float* __restrict__ bih) {
    extern __shared__ float sm[];
    float* xs = sm;            // [64][132]
    float* ws = sm + 64 * 132; // [64][132]
    const int m0 = blockIdx.x * 64;
    const int g0 = blockIdx.y * 64;
    const int tid = threadIdx.x;

    for (int i = tid; i < 64 * 132; i += 256) {
        int r = i / 132, c = i - r * 132;
        xs[i] = (c < 129) ? x[(size_t)(m0 + r) * 129 + c] : 0.f;
    }
    for (int i = tid; i < 64 * 132; i += 256) {
        int r = i / 132, c = i - r * 132;
        ws[i] = (c < 129) ? Wih[(size_t)(g0 + r) * 129 + c] : 0.f;
    }
    __syncthreads();

    const int ty = tid >> 4, tx = tid & 15;
    u64 acc2[4][4] = {};
    const ulonglong2* xs2 = (const ulonglong2*)xs;
    const ulonglong2* ws2 = (const ulonglong2*)ws;

#pragma unroll 3
    for (int k = 0; k < 33; k++) {
        ulonglong2 xv[4], wv[4];
#pragma unroll
        for (int i = 0; i < 4; i++) xv[i] = xs2[(4 * ty + i) * 33 + k];
#pragma unroll
        for (int j = 0; j < 4; j++) wv[j] = ws2[(4 * tx + j) * 33 + k];
#pragma unroll
        for (int i = 0; i < 4; i++)
#pragma unroll
            for (int j = 0; j < 4; j++) {
                fma2(acc2[i][j], xv[i].x, wv[j].x);
                fma2(acc2[i][j], xv[i].y, wv[j].y);
            }
    }

#pragma unroll
    for (int i = 0; i < 4; i++)
#pragma unroll
        for (int j = 0; j < 4; j++) {
            int g = g0 + 4 * tx + j;
            g_xg[(size_t)(m0 + 4 * ty + i) * 512 + g] = hsum2(acc2[i][j]) + bih[g];
        }
}

// ---------------- K2: LSTM — fp16 streamed weights (R11 WIN) ---------------
__global__ void __launch_bounds__(256, 1)
k_lstm7(const float* __restrict__ Whh, const float* __restrict__ bhh) {
    extern __shared__ float sm[];
    uint2* wshh = (uint2*)sm;             // 24 slots * 256 threads * uint2 (4 fp16)
    float* hb   = sm + 24 * 256 * 2;      // [2][128] double-buffered h

    const int b = blockIdx.x;
    const int t = threadIdx.x;
    const int j = t >> 1;
    const bool odd = (t & 1);
    const int gA = odd ? (128 + j) : j;
    const int gB = gA + 256;

    const ulonglong2* WA = (const ulonglong2*)(Whh + (size_t)gA * 128);
    const ulonglong2* WB = (const ulonglong2*)(Whh + (size_t)gB * 128);
    ulonglong2 wA[20], wB[20];
#pragma unroll
    for (int k = 0; k < 20; k++) { wA[k] = WA[k]; wB[k] = WB[k]; }
    {
        const float4* WA4 = (const float4*)WA;
        const float4* WB4 = (const float4*)WB;
#pragma unroll
        for (int k = 0; k < 12; k++) {
            float4 wa = WA4[20 + k];
            float4 wb = WB4[20 + k];
            wshh[k * 256 + t]        = make_uint2(f2h2(wa.x, wa.y), f2h2(wa.z, wa.w));
            wshh[(12 + k) * 256 + t] = make_uint2(f2h2(wb.x, wb.y), f2h2(wb.z, wb.w));
        }
    }
    const float bA = bhh[gA], bB = bhh[gB];

    if (t < 128) hb[t] = 0.f;
    float c = 0.f;

    const float* xgp = g_xg + (size_t)b * 2048 * 512;
    float xgA = xgp[gA], xgB = xgp[gB];
    __syncthreads();

    for (int s = 0; s < 2048; s++) {
        float nA = 0.f, nB = 0.f;
        if (s + 1 < 2048) {
            nA = xgp[(size_t)(s + 1) * 512 + gA];
            nB = xgp[(size_t)(s + 1) * 512 + gB];
        }

        const ulonglong2* h2 = (const ulonglong2*)(hb + (s & 1) * 128);
        u64 a0 = 0ull, a1 = 0ull, d0 = 0ull, d1 = 0ull;
#pragma unroll
        for (int k = 0; k < 20; k++) {
            ulonglong2 hv = h2[k];
            fma2(a0, wA[k].x, hv.x); fma2(a1, wA[k].y, hv.y);
            fma2(d0, wB[k].x, hv.x); fma2(d1, wB[k].y, hv.y);
        }
#pragma unroll
        for (int k = 0; k < 12; k++) {
            ulonglong2 hv = h2[20 + k];
            uint2 wa = wshh[k * 256 + t];
            uint2 wb = wshh[(12 + k) * 256 + t];
            fma2(a0, h2f2(wa.x), hv.x); fma2(a1, h2f2(wa.y), hv.y);
            fma2(d0, h2f2(wb.x), hv.x); fma2(d1, h2f2(wb.y), hv.y);
        }
        float a = hsum2(a0) + hsum2(a1);
        float d = hsum2(d0) + hsum2(d1);

        float pre0 = a + xgA + bA;
        float pre1 = d + xgB + bB;
        float q0 = __shfl_xor_sync(0xffffffffu, pre0, 1);
        float q1 = __shfl_xor_sync(0xffffffffu, pre1, 1);
        float ip, fp, gp, op;
        if (!odd) { ip = pre0; gp = pre1; fp = q0;   op = q1;   }
        else      { ip = q0;   gp = q1;   fp = pre0; op = pre1; }

        c = sigf(fp) * c + sigf(ip) * tanh_fast(gp);
        float h = sigf(op) * tanh_fast(c);

        float* hn = hb + ((s + 1) & 1) * 128;
        if (!odd) {
            hn[j] = h;
            g_lstm[((size_t)b * 2048 + s) * 128 + j] = h;
        }
        xgA = nA; xgB = nB;
        __syncthreads();
    }
}

// ---------------- K3: flash attention, tf32 mma, permuted cols (LDS.64) ----
__global__ void __launch_bounds__(128) k_attn() {
    extern __shared__ float sm[];
    float* qs = sm;                 // [64][132] tf32(q/sqrt129), permuted cols
    float* ks = sm + 64 * 132;      // [64][132] tf32 K==V chunk, permuted cols
    float* ps = ks + 64 * 132;      // [64][68]  tf32 probs (unpermuted)

    const int b  = blockIdx.y;
    const int r0 = blockIdx.x * 64;
    const float* base = g_lstm + (size_t)b * 2048 * 128;
    const int tid  = threadIdx.x;
    const int warp = tid >> 5, lane = tid & 31;
    const int gid  = lane >> 2, tig = lane & 3;
    const int wr   = warp * 16;
    const int pg   = ((gid & 3) << 1) | (gid >> 2);   // perm of gid within 8-group
    const float rs = 0.08804509063256238f; // 1/sqrt(129)

    {   // stage q tile: scale + tf32 + column permutation
        const float4* qg = (const float4*)(base + (size_t)r0 * 128);
        for (int i = tid; i < 2048; i += 128) {
            int row = i >> 5, c4 = (i & 31) * 4;
            float4 v = qg[row * 32 + (i & 31)];
            float* dst = qs + row * 132;
            dst[permc(c4 + 0)] = __uint_as_float(tf32of(v.x * rs));
            dst[permc(c4 + 1)] = __uint_as_float(tf32of(v.y * rs));
            dst[permc(c4 + 2)] = __uint_as_float(tf32of(v.z * rs));
            dst[permc(c4 + 3)] = __uint_as_float(tf32of(v.w * rs));
        }
    }

    float m0 = -1e30f, m1 = -1e30f, l0 = 0.f, l1 = 0.f;
    float o[16][4];
#pragma unroll
    for (int n = 0; n < 16; n++) { o[n][0]=0.f; o[n][1]=0.f; o[n][2]=0.f; o[n][3]=0.f; }

    const unsigned* ksu = (const unsigned*)ks;

    for (int kt = 0; kt < 32; kt++) {
        __syncthreads();
        {   // stage K/V chunk: tf32 + permutation
            const float4* kg = (const float4*)(base + (size_t)kt * 64 * 128);
            for (int i = tid; i < 2048; i += 128) {
                int row = i >> 5, c4 = (i & 31) * 4;
                float4 v = kg[row * 32 + (i & 31)];
                float* dst = ks + row * 132;
                dst[permc(c4 + 0)] = __uint_as_float(tf32of(v.x));
                dst[permc(c4 + 1)] = __uint_as_float(tf32of(v.y));
                dst[permc(c4 + 2)] = __uint_as_float(tf32of(v.z));
                dst[permc(c4 + 3)] = __uint_as_float(tf32of(v.w));
            }
        }
        __syncthreads();

        // phase 1: S(16x64) = Q @ K^T — LDS.64 fragment loads
        float s[8][4];
#pragma unroll
        for (int n = 0; n < 8; n++) { s[n][0]=0.f; s[n][1]=0.f; s[n][2]=0.f; s[n][3]=0.f; }
#pragma unroll
        for (int kk = 0; kk < 16; kk++) {
            const int coff = kk * 8 + 2 * tig;
            uint2 va0 = *(const uint2*)(qs + (wr + gid)     * 132 + coff);
            uint2 va1 = *(const uint2*)(qs + (wr + gid + 8) * 132 + coff);
            unsigned a[4] = {va0.x, va1.x, va0.y, va1.y};
#pragma unroll
            for (int n = 0; n < 8; n++) {
                uint2 vb = *(const uint2*)(ks + (n * 8 + gid) * 132 + coff);
                mma_tf32(s[n], a, vb.x, vb.y);
            }
        }

        // online softmax (S columns = keys, unpermuted)
        float vm0 = -1e30f, vm1 = -1e30f;
#pragma unroll
        for (int n = 0; n < 8; n++) {
            vm0 = fmaxf(vm0, fmaxf(s[n][0], s[n][1]));
            vm1 = fmaxf(vm1, fmaxf(s[n][2], s[n][3]));
        }
        vm0 = fmaxf(vm0, __shfl_xor_sync(0xffffffffu, vm0, 1));
        vm0 = fmaxf(vm0, __shfl_xor_sync(0xffffffffu, vm0, 2));
        vm1 = fmaxf(vm1, __shfl_xor_sync(0xffffffffu, vm1, 1));
        vm1 = fmaxf(vm1, __shfl_xor_sync(0xffffffffu, vm1, 2));
        float nm0 = fmaxf(m0, vm0), nm1 = fmaxf(m1, vm1);

        float sum0 = 0.f, sum1 = 0.f;
#pragma unroll
        for (int n = 0; n < 8; n++) {
            float p0 = __expf(s[n][0] - nm0);
            float p1 = __expf(s[n][1] - nm0);
            float p2 = __expf(s[n][2] - nm1);
            float p3 = __expf(s[n][3] - nm1);
            sum0 += p0 + p1; sum1 += p2 + p3;
            float* pp = ps + (wr + gid) * 68 + n * 8 + 2 * tig;
            pp[0] = __uint_as_float(tf32of(p0));
            pp[1] = __uint_as_float(tf32of(p1));
            float* pq = ps + (wr + gid + 8) * 68 + n * 8 + 2 * tig;
            pq[0] = __uint_as_float(tf32of(p2));
            pq[1] = __uint_as_float(tf32of(p3));
        }
        sum0 += __shfl_xor_sync(0xffffffffu, sum0, 1);
        sum0 += __shfl_xor_sync(0xffffffffu, sum0, 2);
        sum1 += __shfl_xor_sync(0xffffffffu, sum1, 1);
        sum1 += __shfl_xor_sync(0xffffffffu, sum1, 2);
        float alpha0 = __expf(m0 - nm0), alpha1 = __expf(m1 - nm1);
        l0 = l0 * alpha0 + sum0; m0 = nm0;
        l1 = l1 * alpha1 + sum1; m1 = nm1;
        __syncwarp();

        // phase 2: O(16x128) += P @ V (V dims read through permutation)
#pragma unroll
        for (int n = 0; n < 16; n++) {
            o[n][0] *= alpha0; o[n][1] *= alpha0;
            o[n][2] *= alpha1; o[n][3] *= alpha1;
        }
        const unsigned* psu = (const unsigned*)ps;
#pragma unroll
        for (int kk = 0; kk < 8; kk++) {
            unsigned pa[4];
            pa[0] = psu[(wr + gid)     * 68 + kk * 8 + tig];
            pa[1] = psu[(wr + gid + 8) * 68 + kk * 8 + tig];
            pa[2] = psu[(wr + gid)     * 68 + kk * 8 + tig + 4];
            pa[3] = psu[(wr + gid + 8) * 68 + kk * 8 + tig + 4];
#pragma unroll
            for (int n = 0; n < 16; n++) {
                unsigned b0 = ksu[(kk * 8 + tig)     * 132 + n * 8 + pg];
                unsigned b1 = ksu[(kk * 8 + tig + 4) * 132 + n * 8 + pg];
                mma_tf32(o[n], pa, b0, b1);
            }
        }
    }

    // epilogue (o columns are logical dims — unchanged)
    float inv0 = 1.f / l0, inv1 = 1.f / l1;
    int row0 = r0 + wr + gid, row1 = row0 + 8;
    float* d0 = g_ctx + ((size_t)b * 2048 + row0) * 128;
    float* d1 = g_ctx + ((size_t)b * 2048 + row1) * 128;
#pragma unroll
    for (int n = 0; n < 16; n++) {
        int cc = n * 8 + 2 * tig;
        *(float2*)(d0 + cc) = make_float2(o[n][0] * inv0, o[n][1] * inv0);
        *(float2*)(d1 + cc) = make_float2(o[n][2] * inv1, o[n][3] * inv1);
    }
}

// ---------------- K4: concat(context, RBF kernel feature), pad to 132 ------
__global__ void k_feat(const float* __restrict__ x, const float* __restrict__ pr) {
    const int tid = threadIdx.x;
    const int warp = tid >> 5, lane = tid & 31;
    const size_t mrow = (size_t)blockIdx.x * 8 + warp;

    const float4* c4 = (const float4*)(g_ctx + mrow * 128);
    float4* o4 = (float4*)(g_ha + mrow * 132);
    o4[lane] = c4[lane];

    const float* xr = x  + mrow * 129;
    const float* pp = pr + mrow * 129;
    float ss = 0.f;
    for (int j2 = lane; j2 < 129; j2 += 32) {
        float d = xr[j2] - pp[j2];
        ss += d * d;
    }
#pragma unroll
    for (int dd = 16; dd; dd >>= 1) ss += __shfl_xor_sync(0xffffffffu, ss, dd);
    if (lane == 0)      g_ha[mrow * 132 + 128] = __expf(-ss);
    else if (lane < 4)  g_ha[mrow * 132 + 128 + lane] = 0.f;
}

// ---------------- K5: one MLP layer h = relu(h @ Wc[l]^T + bc[l]) — PROVEN -
__global__ void k_mlp(const float* __restrict__ Wc, const float* __restrict__ bc, int l) {
    extern __shared__ float sm[];
    float* Wsh  = sm;              // [132][134]
    float* insh = sm + 132 * 134;  // [64][132]
    const float* in  = (l & 1) ? g_hb : g_ha;
    float*       out = (l & 1) ? g_ha : g_hb;

    const int m0 = blockIdx.x * 64;
    const int tid = threadIdx.x;
    const float* W  = Wc + (size_t)l * 129 * 129;
    const float* bb = bc + (size_t)l * 129;

    for (int i = tid; i < 132 * 134; i += 256) {
        int r = i / 134, c = i - r * 134;
        Wsh[i] = (r < 129 && c < 129) ? W[r * 129 + c] : 0.f;
    }
    for (int i = tid; i < 64 * 132; i += 256)
        insh[i] = in[(size_t)m0 * 132 + i];
    __syncthreads();

    const int warp = tid >> 5, lane = tid & 31;
    const int rb = warp * 8;
    const u64* W2 = (const u64*)Wsh;   // row stride 67 pairs

#pragma unroll
    for (int q = 0; q < 2; q++) {
        u64 acc2[4][5] = {};
        const int r0 = rb + 4 * q;
        const u64* h0p = (const u64*)(insh + (r0 + 0) * 132);
        const u64* h1p = (const u64*)(insh + (r0 + 1) * 132);
        const u64* h2p = (const u64*)(insh + (r0 + 2) * 132);
        const u64* h3p = (const u64*)(insh + (r0 + 3) * 132);
#pragma unroll 2
        for (int jp = 0; jp < 66; jp++) {
            u64 h0 = h0p[jp], h1 = h1p[jp], h2 = h2p[jp], h3 = h3p[jp];
#pragma unroll
            for (int cg = 0; cg < 5; cg++) {
                int cc = lane + 32 * cg;
                if (cc < 132) {
                    u64 w = W2[cc * 67 + jp];
                    fma2(acc2[0][cg], h0, w); fma2(acc2[1][cg], h1, w);
                    fma2(acc2[2][cg], h2, w); fma2(acc2[3][cg], h3, w);
                }
            }
        }
#pragma unroll
        for (int cg = 0; cg < 5; cg++) {
            int cc = lane + 32 * cg;
            if (cc < 132) {
                float bv = (cc < 129) ? bb[cc] : 0.f;
#pragma unroll
                for (int i = 0; i < 4; i++)
                    out[(size_t)(m0 + rb + 4 * q + i) * 132 + cc] =
                        fmaxf(hsum2(acc2[i][cg]) + bv, 0.f);
            }
        }
    }
}

// ---------------- K6: head + log_softmax -----------------------------------
__global__ void k_head(const float* __restrict__ Wh, const float* __restrict__ bh,
                       float* __restrict__ out) {
    const int tid = threadIdx.x;
    const int warp = tid >> 5, lane = tid & 31;
    const size_t mrow = (size_t)blockIdx.x * 8 + warp;
    const float* hr = g_ha + mrow * 132;

    float s0 = 0.f, s1 = 0.f;
    for (int j2 = lane; j2 < 129; j2 += 32) {
        float hv = hr[j2];
        s0 += hv * Wh[j2];
        s1 += hv * Wh[129 + j2];
    }
#pragma unroll
    for (int dd = 16; dd; dd >>= 1) {
        s0 += __shfl_xor_sync(0xffffffffu, s0, dd);
        s1 += __shfl_xor_sync(0xffffffffu, s1, dd);
    }
    if (lane == 0) {
        s0 += bh[0]; s1 += bh[1];
        float mx = fmaxf(s0, s1);
        float lse = mx + logf(__expf(s0 - mx) + __expf(s1 - mx));
        out[2 * mrow]     = s0 - lse;
        out[2 * mrow + 1] = s1 - lse;
    }
}

// ---------------- launch ---------------------------------------------------
extern "C" void kernel_launch(void* const* d_in, const int* in_sizes, int n_in,
                              void* d_out, int out_size) {
    const float* x     = (const float*)d_in[0];
    const float* proto = (const float*)d_in[1];
    const float* Wih   = (const float*)d_in[2];
    const float* Whh   = (const float*)d_in[3];
    const float* bih   = (const float*)d_in[4];
    const float* bhh   = (const float*)d_in[5];
    const float* Wc    = (const float*)d_in[6];
    const float* bc    = (const float*)d_in[7];
    const float* Wh    = (const float*)d_in[8];
    const float* bh    = (const float*)d_in[9];
    float* out = (float*)d_out;

    const int smem_xg   = 2 * 64 * 132 * 4;                 // 67584
    const int smem_lstm = 24 * 256 * 8 + 2 * 128 * 4;       // 50176
    const int smem_attn = (2 * 64 * 132 + 64 * 68) * 4;     // 84992
    const int smem_mlp  = (132 * 134 + 64 * 132) * 4;       // 104544

    cudaFuncSetAttribute(k_xg,    cudaFuncAttributeMaxDynamicSharedMemorySize, smem_xg);
    cudaFuncSetAttribute(k_lstm7, cudaFuncAttributeMaxDynamicSharedMemorySize, smem_lstm);
    cudaFuncSetAttribute(k_attn,  cudaFuncAttributeMaxDynamicSharedMemorySize, smem_attn);
    cudaFuncSetAttribute(k_mlp,   cudaFuncAttributeMaxDynamicSharedMemorySize, smem_mlp);

    k_xg  <<<dim3(512, 8), 256, smem_xg>>>(x, Wih, bih);
    k_lstm7<<<16, 256, smem_lstm>>>(Whh, bhh);
    k_nop <<<1, 32>>>();          // shift ncu slot: launch #4 = k_attn
    k_attn<<<dim3(32, 16), 128, smem_attn>>>();
    k_feat<<<4096,         256>>>(x, proto);
    for (int l = 0; l < 4; l++)
        k_mlp<<<512, 256, smem_mlp>>>(Wc, bc, l);
    k_head<<<4096, 256>>>(Wh, bh, out);
}

// round 14
// speedup vs baseline: 1.0402x; 1.0402x over previous
#include <cuda_runtime.h>
#include <cuda_fp16.h>
#include <math.h>
#include <stdint.h>

typedef unsigned long long u64;

// ---------------- scratch (device globals; no allocation allowed) ----------
__device__ float g_xg  [16u*2048u*512u];   // precomputed input gates [B,S,4H]
__device__ float g_lstm[16u*2048u*128u];   // lstm hidden states [B,S,H]
__device__ float g_ctx [16u*2048u*128u];   // attention context [B,S,H]
__device__ float g_ha  [32768u*132u];      // MLP ping buffer (stride 132)
__device__ float g_hb  [32768u*132u];      // MLP pong buffer

__device__ __forceinline__ float sigf(float x) {
    return __fdividef(1.f, 1.f + __expf(-x));
}
__device__ __forceinline__ float tanh_fast(float x) {
    return fmaf(2.f, sigf(2.f * x), -1.f);
}

// packed f32x2 helpers ------------------------------------------------------
__device__ __forceinline__ void fma2(u64& c, u64 a, u64 b) {
    asm("fma.rn.f32x2 %0, %1, %2, %0;" : "+l"(c) : "l"(a), "l"(b));
}
__device__ __forceinline__ u64 pk(float x, float y) {
    u64 r;
    asm("mov.b64 %0, {%1, %2};" : "=l"(r)
        : "r"(__float_as_uint(x)), "r"(__float_as_uint(y)));
    return r;
}
__device__ __forceinline__ float2 upk(u64 v) {
    unsigned lo, hi;
    asm("mov.b64 {%0, %1}, %2;" : "=r"(lo), "=r"(hi) : "l"(v));
    return make_float2(__uint_as_float(lo), __uint_as_float(hi));
}
__device__ __forceinline__ float hsum2(u64 v) { float2 f = upk(v); return f.x + f.y; }
__device__ __forceinline__ u64 h2f2(unsigned h2bits) {   // half2 -> packed f32x2
    __half2 h = *(__half2*)&h2bits;
    float2 f = __half22float2(h);
    return pk(f.x, f.y);
}
__device__ __forceinline__ unsigned f2h2(float x, float y) {
    __half2 h = __floats2half2_rn(x, y);
    return *(unsigned*)&h;
}

// tf32 helpers ---------------------------------------------------------------
__device__ __forceinline__ unsigned tf32of(float f) {
    unsigned u; asm("cvt.rna.tf32.f32 %0, %1;" : "=r"(u) : "f"(f)); return u;
}
__device__ __forceinline__ void mma_tf32(float* c, const unsigned* a,
                                         unsigned b0, unsigned b1) {
    asm volatile(
        "mma.sync.aligned.m16n8k8.row.col.f32.tf32.tf32.f32 "
        "{%0,%1,%2,%3}, {%4,%5,%6,%7}, {%8,%9}, {%0,%1,%2,%3};"
        : "+f"(c[0]), "+f"(c[1]), "+f"(c[2]), "+f"(c[3])
        : "r"(a[0]), "r"(a[1]), "r"(a[2]), "r"(a[3]), "r"(b0), "r"(b1));
}

__global__ void k_nop() {}

// ---------------- K1: xg = x @ W_ih^T + b_ih — PROVEN f32x2 (R4) ----------
__global__ void k_xg(const float* __restrict__ x,
                     const float* __restrict__ Wih,
                     const float* __restrict__ bih) {
    extern __shared__ float sm[];
    float* xs = sm;            // [64][132]
    float* ws = sm + 64 * 132; // [64][132]
    const int m0 = blockIdx.x * 64;
    const int g0 = blockIdx.y * 64;
    const int tid = threadIdx.x;

    for (int i = tid; i < 64 * 132; i += 256) {
        int r = i / 132, c = i - r * 132;
        xs[i] = (c < 129) ? x[(size_t)(m0 + r) * 129 + c] : 0.f;
    }
    for (int i = tid; i < 64 * 132; i += 256) {
        int r = i / 132, c = i - r * 132;
        ws[i] = (c < 129) ? Wih[(size_t)(g0 + r) * 129 + c] : 0.f;
    }
    __syncthreads();

    const int ty = tid >> 4, tx = tid & 15;
    u64 acc2[4][4] = {};
    const ulonglong2* xs2 = (const ulonglong2*)xs;
    const ulonglong2* ws2 = (const ulonglong2*)ws;

#pragma unroll 3
    for (int k = 0; k < 33; k++) {
        ulonglong2 xv[4], wv[4];
#pragma unroll
        for (int i = 0; i < 4; i++) xv[i] = xs2[(4 * ty + i) * 33 + k];
#pragma unroll
        for (int j = 0; j < 4; j++) wv[j] = ws2[(4 * tx + j) * 33 + k];
#pragma unroll
        for (int i = 0; i < 4; i++)
#pragma unroll
            for (int j = 0; j < 4; j++) {
                fma2(acc2[i][j], xv[i].x, wv[j].x);
                fma2(acc2[i][j], xv[i].y, wv[j].y);
            }
    }

#pragma unroll
    for (int i = 0; i < 4; i++)
#pragma unroll
        for (int j = 0; j < 4; j++) {
            int g = g0 + 4 * tx + j;
            g_xg[(size_t)(m0 + 4 * ty + i) * 512 + g] = hsum2(acc2[i][j]) + bih[g];
        }
}

// ---------------- K2: LSTM — fp16 streamed weights (R11 WIN, 1588us) -------
__global__ void __launch_bounds__(256, 1)
k_lstm7(const float* __restrict__ Whh, const float* __restrict__ bhh) {
    extern __shared__ float sm[];
    uint2* wshh = (uint2*)sm;             // 24 slots * 256 threads * uint2 (4 fp16)
    float* hb   = sm + 24 * 256 * 2;      // [2][128] double-buffered h

    const int b = blockIdx.x;
    const int t = threadIdx.x;
    const int j = t >> 1;
    const bool odd = (t & 1);
    const int gA = odd ? (128 + j) : j;
    const int gB = gA + 256;

    const ulonglong2* WA = (const ulonglong2*)(Whh + (size_t)gA * 128);
    const ulonglong2* WB = (const ulonglong2*)(Whh + (size_t)gB * 128);
    ulonglong2 wA[20], wB[20];
#pragma unroll
    for (int k = 0; k < 20; k++) { wA[k] = WA[k]; wB[k] = WB[k]; }
    {
        const float4* WA4 = (const float4*)WA;
        const float4* WB4 = (const float4*)WB;
#pragma unroll
        for (int k = 0; k < 12; k++) {
            float4 wa = WA4[20 + k];
            float4 wb = WB4[20 + k];
            wshh[k * 256 + t]        = make_uint2(f2h2(wa.x, wa.y), f2h2(wa.z, wa.w));
            wshh[(12 + k) * 256 + t] = make_uint2(f2h2(wb.x, wb.y), f2h2(wb.z, wb.w));
        }
    }
    const float bA = bhh[gA], bB = bhh[gB];

    if (t < 128) hb[t] = 0.f;
    float c = 0.f;

    const float* xgp = g_xg + (size_t)b * 2048 * 512;
    float xgA = xgp[gA], xgB = xgp[gB];
    __syncthreads();

    for (int s = 0; s < 2048; s++) {
        float nA = 0.f, nB = 0.f;
        if (s + 1 < 2048) {
            nA = xgp[(size_t)(s + 1) * 512 + gA];
            nB = xgp[(size_t)(s + 1) * 512 + gB];
        }

        const ulonglong2* h2 = (const ulonglong2*)(hb + (s & 1) * 128);
        u64 a0 = 0ull, a1 = 0ull, d0 = 0ull, d1 = 0ull;
#pragma unroll
        for (int k = 0; k < 20; k++) {
            ulonglong2 hv = h2[k];
            fma2(a0, wA[k].x, hv.x); fma2(a1, wA[k].y, hv.y);
            fma2(d0, wB[k].x, hv.x); fma2(d1, wB[k].y, hv.y);
        }
#pragma unroll
        for (int k = 0; k < 12; k++) {
            ulonglong2 hv = h2[20 + k];
            uint2 wa = wshh[k * 256 + t];
            uint2 wb = wshh[(12 + k) * 256 + t];
            fma2(a0, h2f2(wa.x), hv.x); fma2(a1, h2f2(wa.y), hv.y);
            fma2(d0, h2f2(wb.x), hv.x); fma2(d1, h2f2(wb.y), hv.y);
        }
        float a = hsum2(a0) + hsum2(a1);
        float d = hsum2(d0) + hsum2(d1);

        float pre0 = a + xgA + bA;
        float pre1 = d + xgB + bB;
        float q0 = __shfl_xor_sync(0xffffffffu, pre0, 1);
        float q1 = __shfl_xor_sync(0xffffffffu, pre1, 1);
        float ip, fp, gp, op;
        if (!odd) { ip = pre0; gp = pre1; fp = q0;   op = q1;   }
        else      { ip = q0;   gp = q1;   fp = pre0; op = pre1; }

        c = sigf(fp) * c + sigf(ip) * tanh_fast(gp);
        float h = sigf(op) * tanh_fast(c);

        float* hn = hb + ((s + 1) & 1) * 128;
        if (!odd) {
            hn[j] = h;
            g_lstm[((size_t)b * 2048 + s) * 128 + j] = h;
        }
        xgA = nA; xgB = nB;
        __syncthreads();
    }
}

// ---------------- K3: flash attention, tf32 mma.sync — PROVEN (R4, 340us) --
__global__ void __launch_bounds__(128) k_attn() {
    extern __shared__ float sm[];
    float* qs = sm;                 // [64][132] tf32 bits of q * 1/sqrt(129)
    float* ks = sm + 64 * 132;      // [64][132] tf32 bits of K==V chunk
    float* ps = ks + 64 * 132;      // [64][68]  tf32 probs

    const int b  = blockIdx.y;
    const int r0 = blockIdx.x * 64;
    const float* base = g_lstm + (size_t)b * 2048 * 128;
    const int tid  = threadIdx.x;
    const int warp = tid >> 5, lane = tid & 31;
    const int gid  = lane >> 2, tig = lane & 3;
    const int wr   = warp * 16;
    const float rs = 0.08804509063256238f; // 1/sqrt(129)

    {   // stage q tile: scale + tf32-round
        const float4* qg = (const float4*)(base + (size_t)r0 * 128);
        float4* qs4 = (float4*)qs;
        for (int i = tid; i < 2048; i += 128) {
            int row = i >> 5, c = i & 31;
            float4 v = qg[row * 32 + c];
            v.x = __uint_as_float(tf32of(v.x * rs));
            v.y = __uint_as_float(tf32of(v.y * rs));
            v.z = __uint_as_float(tf32of(v.z * rs));
            v.w = __uint_as_float(tf32of(v.w * rs));
            qs4[row * 33 + c] = v;
        }
    }

    float m0 = -1e30f, m1 = -1e30f, l0 = 0.f, l1 = 0.f;
    float o[16][4];
#pragma unroll
    for (int n = 0; n < 16; n++) { o[n][0]=0.f; o[n][1]=0.f; o[n][2]=0.f; o[n][3]=0.f; }

    const unsigned* qsu = (const unsigned*)qs;
    const unsigned* ksu = (const unsigned*)ks;

    for (int kt = 0; kt < 32; kt++) {
        __syncthreads();
        {   // stage K/V chunk as tf32
            const float4* kg = (const float4*)(base + (size_t)kt * 64 * 128);
            float4* ks4 = (float4*)ks;
            for (int i = tid; i < 2048; i += 128) {
                int row = i >> 5, c = i & 31;
                float4 v = kg[row * 32 + c];
                v.x = __uint_as_float(tf32of(v.x));
                v.y = __uint_as_float(tf32of(v.y));
                v.z = __uint_as_float(tf32of(v.z));
                v.w = __uint_as_float(tf32of(v.w));
                ks4[row * 33 + c] = v;
            }
        }
        __syncthreads();

        // phase 1: S(16x64) = Q @ K^T
        float s[8][4];
#pragma unroll
        for (int n = 0; n < 8; n++) { s[n][0]=0.f; s[n][1]=0.f; s[n][2]=0.f; s[n][3]=0.f; }
#pragma unroll
        for (int kk = 0; kk < 16; kk++) {
            unsigned a[4];
            int cc = kk * 8 + tig;
            a[0] = qsu[(wr + gid)     * 132 + cc];
            a[1] = qsu[(wr + gid + 8) * 132 + cc];
            a[2] = qsu[(wr + gid)     * 132 + cc + 4];
            a[3] = qsu[(wr + gid + 8) * 132 + cc + 4];
#pragma unroll
            for (int n = 0; n < 8; n++) {
                unsigned b0 = ksu[(n * 8 + gid) * 132 + cc];
                unsigned b1 = ksu[(n * 8 + gid) * 132 + cc + 4];
                mma_tf32(s[n], a, b0, b1);
            }
        }

        // online softmax
        float vm0 = -1e30f, vm1 = -1e30f;
#pragma unroll
        for (int n = 0; n < 8; n++) {
            vm0 = fmaxf(vm0, fmaxf(s[n][0], s[n][1]));
            vm1 = fmaxf(vm1, fmaxf(s[n][2], s[n][3]));
        }
        vm0 = fmaxf(vm0, __shfl_xor_sync(0xffffffffu, vm0, 1));
        vm0 = fmaxf(vm0, __shfl_xor_sync(0xffffffffu, vm0, 2));
        vm1 = fmaxf(vm1, __shfl_xor_sync(0xffffffffu, vm1, 1));
        vm1 = fmaxf(vm1, __shfl_xor_sync(0xffffffffu, vm1, 2));
        float nm0 = fmaxf(m0, vm0), nm1 = fmaxf(m1, vm1);

        float sum0 = 0.f, sum1 = 0.f;
#pragma unroll
        for (int n = 0; n < 8; n++) {
            float p0 = __expf(s[n][0] - nm0);
            float p1 = __expf(s[n][1] - nm0);
            float p2 = __expf(s[n][2] - nm1);
            float p3 = __expf(s[n][3] - nm1);
            sum0 += p0 + p1; sum1 += p2 + p3;
            float* pp = ps + (wr + gid) * 68 + n * 8 + 2 * tig;
            pp[0] = __uint_as_float(tf32of(p0));
            pp[1] = __uint_as_float(tf32of(p1));
            float* pq = ps + (wr + gid + 8) * 68 + n * 8 + 2 * tig;
            pq[0] = __uint_as_float(tf32of(p2));
            pq[1] = __uint_as_float(tf32of(p3));
        }
        sum0 += __shfl_xor_sync(0xffffffffu, sum0, 1);
        sum0 += __shfl_xor_sync(0xffffffffu, sum0, 2);
        sum1 += __shfl_xor_sync(0xffffffffu, sum1, 1);
        sum1 += __shfl_xor_sync(0xffffffffu, sum1, 2);
        float alpha0 = __expf(m0 - nm0), alpha1 = __expf(m1 - nm1);
        l0 = l0 * alpha0 + sum0; m0 = nm0;
        l1 = l1 * alpha1 + sum1; m1 = nm1;
        __syncwarp();

        // phase 2: O(16x128) += P @ V
#pragma unroll
        for (int n = 0; n < 16; n++) {
            o[n][0] *= alpha0; o[n][1] *= alpha0;
            o[n][2] *= alpha1; o[n][3] *= alpha1;
        }
        const unsigned* psu = (const unsigned*)ps;
#pragma unroll
        for (int kk = 0; kk < 8; kk++) {
            unsigned pa[4];
            pa[0] = psu[(wr + gid)     * 68 + kk * 8 + tig];
            pa[1] = psu[(wr + gid + 8) * 68 + kk * 8 + tig];
            pa[2] = psu[(wr + gid)     * 68 + kk * 8 + tig + 4];
            pa[3] = psu[(wr + gid + 8) * 68 + kk * 8 + tig + 4];
#pragma unroll
            for (int n = 0; n < 16; n++) {
                unsigned b0 = ksu[(kk * 8 + tig)     * 132 + n * 8 + gid];
                unsigned b1 = ksu[(kk * 8 + tig + 4) * 132 + n * 8 + gid];
                mma_tf32(o[n], pa, b0, b1);
            }
        }
    }

    // epilogue
    float inv0 = 1.f / l0, inv1 = 1.f / l1;
    int row0 = r0 + wr + gid, row1 = row0 + 8;
    float* d0 = g_ctx + ((size_t)b * 2048 + row0) * 128;
    float* d1 = g_ctx + ((size_t)b * 2048 + row1) * 128;
#pragma unroll
    for (int n = 0; n < 16; n++) {
        int cc = n * 8 + 2 * tig;
        *(float2*)(d0 + cc) = make_float2(o[n][0] * inv0, o[n][1] * inv0);
        *(float2*)(d1 + cc) = make_float2(o[n][2] * inv1, o[n][3] * inv1);
    }
}

// ---------------- K4: concat(context, RBF kernel feature), pad to 132 ------
__global__ void k_feat(const float* __restrict__ x, const float* __restrict__ pr) {
    const int tid = threadIdx.x;
    const int warp = tid >> 5, lane = tid & 31;
    const size_t mrow = (size_t)blockIdx.x * 8 + warp;

    const float4* c4 = (const float4*)(g_ctx + mrow * 128);
    float4* o4 = (float4*)(g_ha + mrow * 132);
    o4[lane] = c4[lane];

    const float* xr = x  + mrow * 129;
    const float* pp = pr + mrow * 129;
    float ss = 0.f;
    for (int j2 = lane; j2 < 129; j2 += 32) {
        float d = xr[j2] - pp[j2];
        ss += d * d;
    }
#pragma unroll
    for (int dd = 16; dd; dd >>= 1) ss += __shfl_xor_sync(0xffffffffu, ss, dd);
    if (lane == 0)      g_ha[mrow * 132 + 128] = __expf(-ss);
    else if (lane < 4)  g_ha[mrow * 132 + 128 + lane] = 0.f;
}

// ---------------- K5: one MLP layer h = relu(h @ Wc[l]^T + bc[l]) — PROVEN -
__global__ void k_mlp(const float* __restrict__ Wc, const float* __restrict__ bc, int l) {
    extern __shared__ float sm[];
    float* Wsh  = sm;              // [132][134]
    float* insh = sm + 132 * 134;  // [64][132]
    const float* in  = (l & 1) ? g_hb : g_ha;
    float*       out = (l & 1) ? g_ha : g_hb;

    const int m0 = blockIdx.x * 64;
    const int tid = threadIdx.x;
    const float* W  = Wc + (size_t)l * 129 * 129;
    const float* bb = bc + (size_t)l * 129;

    for (int i = tid; i < 132 * 134; i += 256) {
        int r = i / 134, c = i - r * 134;
        Wsh[i] = (r < 129 && c < 129) ? W[r * 129 + c] : 0.f;
    }
    for (int i = tid; i < 64 * 132; i += 256)
        insh[i] = in[(size_t)m0 * 132 + i];
    __syncthreads();

    const int warp = tid >> 5, lane = tid & 31;
    const int rb = warp * 8;
    const u64* W2 = (const u64*)Wsh;   // row stride 67 pairs

#pragma unroll
    for (int q = 0; q < 2; q++) {
        u64 acc2[4][5] = {};
        const int r0 = rb + 4 * q;
        const u64* h0p = (const u64*)(insh + (r0 + 0) * 132);
        const u64* h1p = (const u64*)(insh + (r0 + 1) * 132);
        const u64* h2p = (const u64*)(insh + (r0 + 2) * 132);
        const u64* h3p = (const u64*)(insh + (r0 + 3) * 132);
#pragma unroll 2
        for (int jp = 0; jp < 66; jp++) {
            u64 h0 = h0p[jp], h1 = h1p[jp], h2 = h2p[jp], h3 = h3p[jp];
#pragma unroll
            for (int cg = 0; cg < 5; cg++) {
                int cc = lane + 32 * cg;
                if (cc < 132) {
                    u64 w = W2[cc * 67 + jp];
                    fma2(acc2[0][cg], h0, w); fma2(acc2[1][cg], h1, w);
                    fma2(acc2[2][cg], h2, w); fma2(acc2[3][cg], h3, w);
                }
            }
        }
#pragma unroll
        for (int cg = 0; cg < 5; cg++) {
            int cc = lane + 32 * cg;
            if (cc < 132) {
                float bv = (cc < 129) ? bb[cc] : 0.f;
#pragma unroll
                for (int i = 0; i < 4; i++)
                    out[(size_t)(m0 + rb + 4 * q + i) * 132 + cc] =
                        fmaxf(hsum2(acc2[i][cg]) + bv, 0.f);
            }
        }
    }
}

// ---------------- K6: head + log_softmax -----------------------------------
__global__ void k_head(const float* __restrict__ Wh, const float* __restrict__ bh,
                       float* __restrict__ out) {
    const int tid = threadIdx.x;
    const int warp = tid >> 5, lane = tid & 31;
    const size_t mrow = (size_t)blockIdx.x * 8 + warp;
    const float* hr = g_ha + mrow * 132;

    float s0 = 0.f, s1 = 0.f;
    for (int j2 = lane; j2 < 129; j2 += 32) {
        float hv = hr[j2];
        s0 += hv * Wh[j2];
        s1 += hv * Wh[129 + j2];
    }
#pragma unroll
    for (int dd = 16; dd; dd >>= 1) {
        s0 += __shfl_xor_sync(0xffffffffu, s0, dd);
        s1 += __shfl_xor_sync(0xffffffffu, s1, dd);
    }
    if (lane == 0) {
        s0 += bh[0]; s1 += bh[1];
        float mx = fmaxf(s0, s1);
        float lse = mx + logf(__expf(s0 - mx) + __expf(s1 - mx));
        out[2 * mrow]     = s0 - lse;
        out[2 * mrow + 1] = s1 - lse;
    }
}

// ---------------- launch ---------------------------------------------------
extern "C" void kernel_launch(void* const* d_in, const int* in_sizes, int n_in,
                              void* d_out, int out_size) {
    const float* x     = (const float*)d_in[0];
    const float* proto = (const float*)d_in[1];
    const float* Wih   = (const float*)d_in[2];
    const float* Whh   = (const float*)d_in[3];
    const float* bih   = (const float*)d_in[4];
    const float* bhh   = (const float*)d_in[5];
    const float* Wc    = (const float*)d_in[6];
    const float* bc    = (const float*)d_in[7];
    const float* Wh    = (const float*)d_in[8];
    const float* bh    = (const float*)d_in[9];
    float* out = (float*)d_out;

    const int smem_xg   = 2 * 64 * 132 * 4;                 // 67584
    const int smem_lstm = 24 * 256 * 8 + 2 * 128 * 4;       // 50176
    const int smem_attn = (2 * 64 * 132 + 64 * 68) * 4;     // 84992
    const int smem_mlp  = (132 * 134 + 64 * 132) * 4;       // 104544

    cudaFuncSetAttribute(k_xg,    cudaFuncAttributeMaxDynamicSharedMemorySize, smem_xg);
    cudaFuncSetAttribute(k_lstm7, cudaFuncAttributeMaxDynamicSharedMemorySize, smem_lstm);
    cudaFuncSetAttribute(k_attn,  cudaFuncAttributeMaxDynamicSharedMemorySize, smem_attn);
    cudaFuncSetAttribute(k_mlp,   cudaFuncAttributeMaxDynamicSharedMemorySize, smem_mlp);

    k_xg  <<<dim3(512, 8), 256, smem_xg>>>(x, Wih, bih);
    k_lstm7<<<16, 256, smem_lstm>>>(Whh, bhh);
    k_nop <<<1, 32>>>();          // shift ncu slot: launch #4 = k_attn
    k_attn<<<dim3(32, 16), 128, smem_attn>>>();
    k_feat<<<4096,         256>>>(x, proto);
    for (int l = 0; l < 4; l++)
        k_mlp<<<512, 256, smem_mlp>>>(Wc, bc, l);
    k_head<<<4096, 256>>>(Wh, bh, out);
}

// round 15
// speedup vs baseline: 1.0485x; 1.0080x over previous
#include <cuda_runtime.h>
#include <cuda_fp16.h>
#include <math.h>
#include <stdint.h>

typedef unsigned long long u64;

// ---------------- scratch (device globals; no allocation allowed) ----------
__device__ float g_xg  [16u*2048u*512u];   // precomputed input gates [B,S,4H]
__device__ float g_lstm[16u*2048u*128u];   // lstm hidden states [B,S,H]
__device__ float g_ctx [16u*2048u*128u];   // attention context [B,S,H]
__device__ float g_ha  [32768u*132u];      // MLP ping buffer (stride 132)
__device__ float g_hb  [32768u*132u];      // MLP pong buffer

__device__ __forceinline__ float sigf(float x) {
    return __fdividef(1.f, 1.f + __expf(-x));
}
__device__ __forceinline__ float tanh_fast(float x) {
    return fmaf(2.f, sigf(2.f * x), -1.f);
}

// packed f32x2 helpers ------------------------------------------------------
__device__ __forceinline__ void fma2(u64& c, u64 a, u64 b) {
    asm("fma.rn.f32x2 %0, %1, %2, %0;" : "+l"(c) : "l"(a), "l"(b));
}
__device__ __forceinline__ u64 pk(float x, float y) {
    u64 r;
    asm("mov.b64 %0, {%1, %2};" : "=l"(r)
        : "r"(__float_as_uint(x)), "r"(__float_as_uint(y)));
    return r;
}
__device__ __forceinline__ float2 upk(u64 v) {
    unsigned lo, hi;
    asm("mov.b64 {%0, %1}, %2;" : "=r"(lo), "=r"(hi) : "l"(v));
    return make_float2(__uint_as_float(lo), __uint_as_float(hi));
}
__device__ __forceinline__ float hsum2(u64 v) { float2 f = upk(v); return f.x + f.y; }
__device__ __forceinline__ u64 h2f2(unsigned h2bits) {   // half2 -> packed f32x2
    __half2 h = *(__half2*)&h2bits;
    float2 f = __half22float2(h);
    return pk(f.x, f.y);
}
__device__ __forceinline__ unsigned f2h2(float x, float y) {
    __half2 h = __floats2half2_rn(x, y);
    return *(unsigned*)&h;
}

// tf32 helpers ---------------------------------------------------------------
__device__ __forceinline__ unsigned tf32of(float f) {
    unsigned u; asm("cvt.rna.tf32.f32 %0, %1;" : "=r"(u) : "f"(f)); return u;
}
__device__ __forceinline__ void mma_tf32(float* c, const unsigned* a,
                                         unsigned b0, unsigned b1) {
    asm volatile(
        "mma.sync.aligned.m16n8k8.row.col.f32.tf32.tf32.f32 "
        "{%0,%1,%2,%3}, {%4,%5,%6,%7}, {%8,%9}, {%0,%1,%2,%3};"
        : "+f"(c[0]), "+f"(c[1]), "+f"(c[2]), "+f"(c[3])
        : "r"(a[0]), "r"(a[1]), "r"(a[2]), "r"(a[3]), "r"(b0), "r"(b1));
}

__global__ void k_nop() {}

// ---------------- K1: xg = x @ W_ih^T + b_ih — PROVEN f32x2 (R4) ----------
__global__ void k_xg(const float* __restrict__ x,
                     const float* __restrict__ Wih,
                     const float* __restrict__ bih) {
    extern __shared__ float sm[];
    float* xs = sm;            // [64][132]
    float* ws = sm + 64 * 132; // [64][132]
    const int m0 = blockIdx.x * 64;
    const int g0 = blockIdx.y * 64;
    const int tid = threadIdx.x;

    for (int i = tid; i < 64 * 132; i += 256) {
        int r = i / 132, c = i - r * 132;
        xs[i] = (c < 129) ? x[(size_t)(m0 + r) * 129 + c] : 0.f;
    }
    for (int i = tid; i < 64 * 132; i += 256) {
        int r = i / 132, c = i - r * 132;
        ws[i] = (c < 129) ? Wih[(size_t)(g0 + r) * 129 + c] : 0.f;
    }
    __syncthreads();

    const int ty = tid >> 4, tx = tid & 15;
    u64 acc2[4][4] = {};
    const ulonglong2* xs2 = (const ulonglong2*)xs;
    const ulonglong2* ws2 = (const ulonglong2*)ws;

#pragma unroll 3
    for (int k = 0; k < 33; k++) {
        ulonglong2 xv[4], wv[4];
#pragma unroll
        for (int i = 0; i < 4; i++) xv[i] = xs2[(4 * ty + i) * 33 + k];
#pragma unroll
        for (int j = 0; j < 4; j++) wv[j] = ws2[(4 * tx + j) * 33 + k];
#pragma unroll
        for (int i = 0; i < 4; i++)
#pragma unroll
            for (int j = 0; j < 4; j++) {
                fma2(acc2[i][j], xv[i].x, wv[j].x);
                fma2(acc2[i][j], xv[i].y, wv[j].y);
            }
    }

#pragma unroll
    for (int i = 0; i < 4; i++)
#pragma unroll
        for (int j = 0; j < 4; j++) {
            int g = g0 + 4 * tx + j;
            g_xg[(size_t)(m0 + 4 * ty + i) * 512 + g] = hsum2(acc2[i][j]) + bih[g];
        }
}

// ---------------- K2: LSTM — fp16 streamed weights (R11 WIN, 1588us) -------
__global__ void __launch_bounds__(256, 1)
k_lstm7(const float* __restrict__ Whh, const float* __restrict__ bhh) {
    extern __shared__ float sm[];
    uint2* wshh = (uint2*)sm;             // 24 slots * 256 threads * uint2 (4 fp16)
    float* hb   = sm + 24 * 256 * 2;      // [2][128] double-buffered h

    const int b = blockIdx.x;
    const int t = threadIdx.x;
    const int j = t >> 1;
    const bool odd = (t & 1);
    const int gA = odd ? (128 + j) : j;
    const int gB = gA + 256;

    const ulonglong2* WA = (const ulonglong2*)(Whh + (size_t)gA * 128);
    const ulonglong2* WB = (const ulonglong2*)(Whh + (size_t)gB * 128);
    ulonglong2 wA[20], wB[20];
#pragma unroll
    for (int k = 0; k < 20; k++) { wA[k] = WA[k]; wB[k] = WB[k]; }
    {
        const float4* WA4 = (const float4*)WA;
        const float4* WB4 = (const float4*)WB;
#pragma unroll
        for (int k = 0; k < 12; k++) {
            float4 wa = WA4[20 + k];
            float4 wb = WB4[20 + k];
            wshh[k * 256 + t]        = make_uint2(f2h2(wa.x, wa.y), f2h2(wa.z, wa.w));
            wshh[(12 + k) * 256 + t] = make_uint2(f2h2(wb.x, wb.y), f2h2(wb.z, wb.w));
        }
    }
    const float bA = bhh[gA], bB = bhh[gB];

    if (t < 128) hb[t] = 0.f;
    float c = 0.f;

    const float* xgp = g_xg + (size_t)b * 2048 * 512;
    float xgA = xgp[gA], xgB = xgp[gB];
    __syncthreads();

    for (int s = 0; s < 2048; s++) {
        float nA = 0.f, nB = 0.f;
        if (s + 1 < 2048) {
            nA = xgp[(size_t)(s + 1) * 512 + gA];
            nB = xgp[(size_t)(s + 1) * 512 + gB];
        }

        const ulonglong2* h2 = (const ulonglong2*)(hb + (s & 1) * 128);
        u64 a0 = 0ull, a1 = 0ull, d0 = 0ull, d1 = 0ull;
#pragma unroll
        for (int k = 0; k < 20; k++) {
            ulonglong2 hv = h2[k];
            fma2(a0, wA[k].x, hv.x); fma2(a1, wA[k].y, hv.y);
            fma2(d0, wB[k].x, hv.x); fma2(d1, wB[k].y, hv.y);
        }
#pragma unroll
        for (int k = 0; k < 12; k++) {
            ulonglong2 hv = h2[20 + k];
            uint2 wa = wshh[k * 256 + t];
            uint2 wb = wshh[(12 + k) * 256 + t];
            fma2(a0, h2f2(wa.x), hv.x); fma2(a1, h2f2(wa.y), hv.y);
            fma2(d0, h2f2(wb.x), hv.x); fma2(d1, h2f2(wb.y), hv.y);
        }
        float a = hsum2(a0) + hsum2(a1);
        float d = hsum2(d0) + hsum2(d1);

        float pre0 = a + xgA + bA;
        float pre1 = d + xgB + bB;
        float q0 = __shfl_xor_sync(0xffffffffu, pre0, 1);
        float q1 = __shfl_xor_sync(0xffffffffu, pre1, 1);
        float ip, fp, gp, op;
        if (!odd) { ip = pre0; gp = pre1; fp = q0;   op = q1;   }
        else      { ip = q0;   gp = q1;   fp = pre0; op = pre1; }

        c = sigf(fp) * c + sigf(ip) * tanh_fast(gp);
        float h = sigf(op) * tanh_fast(c);

        float* hn = hb + ((s + 1) & 1) * 128;
        if (!odd) {
            hn[j] = h;
            g_lstm[((size_t)b * 2048 + s) * 128 + j] = h;
        }
        xgA = nA; xgB = nB;
        __syncthreads();
    }
}

// ---------------- K3: flash attention, tf32 mma, Q-fragments in registers --
// smem = ks[64][132] + ps[64][68] = 51.2KB -> 2+ CTAs/SM. Q staged through ks
// once, fragments live in 64 regs/thread for the whole kernel.
__global__ void __launch_bounds__(128) k_attn() {
    extern __shared__ float sm[];
    float* ks = sm;                 // [64][132]: q tile during init, then K/V
    float* ps = sm + 64 * 132;      // [64][68]  tf32 probs

    const int b  = blockIdx.y;
    const int r0 = blockIdx.x * 64;
    const float* base = g_lstm + (size_t)b * 2048 * 128;
    const int tid  = threadIdx.x;
    const int warp = tid >> 5, lane = tid & 31;
    const int gid  = lane >> 2, tig = lane & 3;
    const int wr   = warp * 16;
    const float rs = 0.08804509063256238f; // 1/sqrt(129)

    {   // stage q tile into ks: scale + tf32-round
        const float4* qg = (const float4*)(base + (size_t)r0 * 128);
        float4* ks4 = (float4*)ks;
        for (int i = tid; i < 2048; i += 128) {
            int row = i >> 5, c = i & 31;
            float4 v = qg[row * 32 + c];
            v.x = __uint_as_float(tf32of(v.x * rs));
            v.y = __uint_as_float(tf32of(v.y * rs));
            v.z = __uint_as_float(tf32of(v.z * rs));
            v.w = __uint_as_float(tf32of(v.w * rs));
            ks4[row * 33 + c] = v;
        }
    }
    __syncthreads();

    // load Q fragments into registers (64 regs)
    unsigned qf[16][4];
    {
        const unsigned* ksu0 = (const unsigned*)ks;
#pragma unroll
        for (int kk = 0; kk < 16; kk++) {
            int cc = kk * 8 + tig;
            qf[kk][0] = ksu0[(wr + gid)     * 132 + cc];
            qf[kk][1] = ksu0[(wr + gid + 8) * 132 + cc];
            qf[kk][2] = ksu0[(wr + gid)     * 132 + cc + 4];
            qf[kk][3] = ksu0[(wr + gid + 8) * 132 + cc + 4];
        }
    }

    float m0 = -1e30f, m1 = -1e30f, l0 = 0.f, l1 = 0.f;
    float o[16][4];
#pragma unroll
    for (int n = 0; n < 16; n++) { o[n][0]=0.f; o[n][1]=0.f; o[n][2]=0.f; o[n][3]=0.f; }

    const unsigned* ksu = (const unsigned*)ks;

    for (int kt = 0; kt < 32; kt++) {
        __syncthreads();   // protects qf reads (iter 0) / prior phase-2 reads
        {   // stage K/V chunk as tf32
            const float4* kg = (const float4*)(base + (size_t)kt * 64 * 128);
            float4* ks4 = (float4*)ks;
            for (int i = tid; i < 2048; i += 128) {
                int row = i >> 5, c = i & 31;
                float4 v = kg[row * 32 + c];
                v.x = __uint_as_float(tf32of(v.x));
                v.y = __uint_as_float(tf32of(v.y));
                v.z = __uint_as_float(tf32of(v.z));
                v.w = __uint_as_float(tf32of(v.w));
                ks4[row * 33 + c] = v;
            }
        }
        __syncthreads();

        // phase 1: S(16x64) = Q @ K^T  (A from registers)
        float s[8][4];
#pragma unroll
        for (int n = 0; n < 8; n++) { s[n][0]=0.f; s[n][1]=0.f; s[n][2]=0.f; s[n][3]=0.f; }
#pragma unroll
        for (int kk = 0; kk < 16; kk++) {
            int cc = kk * 8 + tig;
#pragma unroll
            for (int n = 0; n < 8; n++) {
                unsigned b0 = ksu[(n * 8 + gid) * 132 + cc];
                unsigned b1 = ksu[(n * 8 + gid) * 132 + cc + 4];
                mma_tf32(s[n], qf[kk], b0, b1);
            }
        }

        // online softmax
        float vm0 = -1e30f, vm1 = -1e30f;
#pragma unroll
        for (int n = 0; n < 8; n++) {
            vm0 = fmaxf(vm0, fmaxf(s[n][0], s[n][1]));
            vm1 = fmaxf(vm1, fmaxf(s[n][2], s[n][3]));
        }
        vm0 = fmaxf(vm0, __shfl_xor_sync(0xffffffffu, vm0, 1));
        vm0 = fmaxf(vm0, __shfl_xor_sync(0xffffffffu, vm0, 2));
        vm1 = fmaxf(vm1, __shfl_xor_sync(0xffffffffu, vm1, 1));
        vm1 = fmaxf(vm1, __shfl_xor_sync(0xffffffffu, vm1, 2));
        float nm0 = fmaxf(m0, vm0), nm1 = fmaxf(m1, vm1);

        float sum0 = 0.f, sum1 = 0.f;
#pragma unroll
        for (int n = 0; n < 8; n++) {
            float p0 = __expf(s[n][0] - nm0);
            float p1 = __expf(s[n][1] - nm0);
            float p2 = __expf(s[n][2] - nm1);
            float p3 = __expf(s[n][3] - nm1);
            sum0 += p0 + p1; sum1 += p2 + p3;
            float* pp = ps + (wr + gid) * 68 + n * 8 + 2 * tig;
            pp[0] = __uint_as_float(tf32of(p0));
            pp[1] = __uint_as_float(tf32of(p1));
            float* pq = ps + (wr + gid + 8) * 68 + n * 8 + 2 * tig;
            pq[0] = __uint_as_float(tf32of(p2));
            pq[1] = __uint_as_float(tf32of(p3));
        }
        sum0 += __shfl_xor_sync(0xffffffffu, sum0, 1);
        sum0 += __shfl_xor_sync(0xffffffffu, sum0, 2);
        sum1 += __shfl_xor_sync(0xffffffffu, sum1, 1);
        sum1 += __shfl_xor_sync(0xffffffffu, sum1, 2);
        float alpha0 = __expf(m0 - nm0), alpha1 = __expf(m1 - nm1);
        l0 = l0 * alpha0 + sum0; m0 = nm0;
        l1 = l1 * alpha1 + sum1; m1 = nm1;
        __syncwarp();   // ps written/read within the same warp only

        // phase 2: O(16x128) += P @ V
#pragma unroll
        for (int n = 0; n < 16; n++) {
            o[n][0] *= alpha0; o[n][1] *= alpha0;
            o[n][2] *= alpha1; o[n][3] *= alpha1;
        }
        const unsigned* psu = (const unsigned*)ps;
#pragma unroll
        for (int kk = 0; kk < 8; kk++) {
            unsigned pa[4];
            pa[0] = psu[(wr + gid)     * 68 + kk * 8 + tig];
            pa[1] = psu[(wr + gid + 8) * 68 + kk * 8 + tig];
            pa[2] = psu[(wr + gid)     * 68 + kk * 8 + tig + 4];
            pa[3] = psu[(wr + gid + 8) * 68 + kk * 8 + tig + 4];
#pragma unroll
            for (int n = 0; n < 16; n++) {
                unsigned b0 = ksu[(kk * 8 + tig)     * 132 + n * 8 + gid];
                unsigned b1 = ksu[(kk * 8 + tig + 4) * 132 + n * 8 + gid];
                mma_tf32(o[n], pa, b0, b1);
            }
        }
    }

    // epilogue
    float inv0 = 1.f / l0, inv1 = 1.f / l1;
    int row0 = r0 + wr + gid, row1 = row0 + 8;
    float* d0 = g_ctx + ((size_t)b * 2048 + row0) * 128;
    float* d1 = g_ctx + ((size_t)b * 2048 + row1) * 128;
#pragma unroll
    for (int n = 0; n < 16; n++) {
        int cc = n * 8 + 2 * tig;
        *(float2*)(d0 + cc) = make_float2(o[n][0] * inv0, o[n][1] * inv0);
        *(float2*)(d1 + cc) = make_float2(o[n][2] * inv1, o[n][3] * inv1);
    }
}

// ---------------- K4: concat(context, RBF kernel feature), pad to 132 ------
__global__ void k_feat(const float* __restrict__ x, const float* __restrict__ pr) {
    const int tid = threadIdx.x;
    const int warp = tid >> 5, lane = tid & 31;
    const size_t mrow = (size_t)blockIdx.x * 8 + warp;

    const float4* c4 = (const float4*)(g_ctx + mrow * 128);
    float4* o4 = (float4*)(g_ha + mrow * 132);
    o4[lane] = c4[lane];

    const float* xr = x  + mrow * 129;
    const float* pp = pr + mrow * 129;
    float ss = 0.f;
    for (int j2 = lane; j2 < 129; j2 += 32) {
        float d = xr[j2] - pp[j2];
        ss += d * d;
    }
#pragma unroll
    for (int dd = 16; dd; dd >>= 1) ss += __shfl_xor_sync(0xffffffffu, ss, dd);
    if (lane == 0)      g_ha[mrow * 132 + 128] = __expf(-ss);
    else if (lane < 4)  g_ha[mrow * 132 + 128 + lane] = 0.f;
}

// ---------------- K5: one MLP layer h = relu(h @ Wc[l]^T + bc[l]) — PROVEN -
__global__ void k_mlp(const float* __restrict__ Wc, const float* __restrict__ bc, int l) {
    extern __shared__ float sm[];
    float* Wsh  = sm;              // [132][134]
    float* insh = sm + 132 * 134;  // [64][132]
    const float* in  = (l & 1) ? g_hb : g_ha;
    float*       out = (l & 1) ? g_ha : g_hb;

    const int m0 = blockIdx.x * 64;
    const int tid = threadIdx.x;
    const float* W  = Wc + (size_t)l * 129 * 129;
    const float* bb = bc + (size_t)l * 129;

    for (int i = tid; i < 132 * 134; i += 256) {
        int r = i / 134, c = i - r * 134;
        Wsh[i] = (r < 129 && c < 129) ? W[r * 129 + c] : 0.f;
    }
    for (int i = tid; i < 64 * 132; i += 256)
        insh[i] = in[(size_t)m0 * 132 + i];
    __syncthreads();

    const int warp = tid >> 5, lane = tid & 31;
    const int rb = warp * 8;
    const u64* W2 = (const u64*)Wsh;   // row stride 67 pairs

#pragma unroll
    for (int q = 0; q < 2; q++) {
        u64 acc2[4][5] = {};
        const int r0 = rb + 4 * q;
        const u64* h0p = (const u64*)(insh + (r0 + 0) * 132);
        const u64* h1p = (const u64*)(insh + (r0 + 1) * 132);
        const u64* h2p = (const u64*)(insh + (r0 + 2) * 132);
        const u64* h3p = (const u64*)(insh + (r0 + 3) * 132);
#pragma unroll 2
        for (int jp = 0; jp < 66; jp++) {
            u64 h0 = h0p[jp], h1 = h1p[jp], h2 = h2p[jp], h3 = h3p[jp];
#pragma unroll
            for (int cg = 0; cg < 5; cg++) {
                int cc = lane + 32 * cg;
                if (cc < 132) {
                    u64 w = W2[cc * 67 + jp];
                    fma2(acc2[0][cg], h0, w); fma2(acc2[1][cg], h1, w);
                    fma2(acc2[2][cg], h2, w); fma2(acc2[3][cg], h3, w);
                }
            }
        }
#pragma unroll
        for (int cg = 0; cg < 5; cg++) {
            int cc = lane + 32 * cg;
            if (cc < 132) {
                float bv = (cc < 129) ? bb[cc] : 0.f;
#pragma unroll
                for (int i = 0; i < 4; i++)
                    out[(size_t)(m0 + rb + 4 * q + i) * 132 + cc] =
                        fmaxf(hsum2(acc2[i][cg]) + bv, 0.f);
            }
        }
    }
}

// ---------------- K6: head + log_softmax -----------------------------------
__global__ void k_head(const float* __restrict__ Wh, const float* __restrict__ bh,
                       float* __restrict__ out) {
    const int tid = threadIdx.x;
    const int warp = tid >> 5, lane = tid & 31;
    const size_t mrow = (size_t)blockIdx.x * 8 + warp;
    const float* hr = g_ha + mrow * 132;

    float s0 = 0.f, s1 = 0.f;
    for (int j2 = lane; j2 < 129; j2 += 32) {
        float hv = hr[j2];
        s0 += hv * Wh[j2];
        s1 += hv * Wh[129 + j2];
    }
#pragma unroll
    for (int dd = 16; dd; dd >>= 1) {
        s0 += __shfl_xor_sync(0xffffffffu, s0, dd);
        s1 += __shfl_xor_sync(0xffffffffu, s1, dd);
    }
    if (lane == 0) {
        s0 += bh[0]; s1 += bh[1];
        float mx = fmaxf(s0, s1);
        float lse = mx + logf(__expf(s0 - mx) + __expf(s1 - mx));
        out[2 * mrow]     = s0 - lse;
        out[2 * mrow + 1] = s1 - lse;
    }
}

// ---------------- launch ---------------------------------------------------
extern "C" void kernel_launch(void* const* d_in, const int* in_sizes, int n_in,
                              void* d_out, int out_size) {
    const float* x     = (const float*)d_in[0];
    const float* proto = (const float*)d_in[1];
    const float* Wih   = (const float*)d_in[2];
    const float* Whh   = (const float*)d_in[3];
    const float* bih   = (const float*)d_in[4];
    const float* bhh   = (const float*)d_in[5];
    const float* Wc    = (const float*)d_in[6];
    const float* bc    = (const float*)d_in[7];
    const float* Wh    = (const float*)d_in[8];
    const float* bh    = (const float*)d_in[9];
    float* out = (float*)d_out;

    const int smem_xg   = 2 * 64 * 132 * 4;                 // 67584
    const int smem_lstm = 24 * 256 * 8 + 2 * 128 * 4;       // 50176
    const int smem_attn = (64 * 132 + 64 * 68) * 4;         // 51200
    const int smem_mlp  = (132 * 134 + 64 * 132) * 4;       // 104544

    cudaFuncSetAttribute(k_xg,    cudaFuncAttributeMaxDynamicSharedMemorySize, smem_xg);
    cudaFuncSetAttribute(k_lstm7, cudaFuncAttributeMaxDynamicSharedMemorySize, smem_lstm);
    cudaFuncSetAttribute(k_attn,  cudaFuncAttributeMaxDynamicSharedMemorySize, smem_attn);
    cudaFuncSetAttribute(k_mlp,   cudaFuncAttributeMaxDynamicSharedMemorySize, smem_mlp);

    k_xg  <<<dim3(512, 8), 256, smem_xg>>>(x, Wih, bih);
    k_lstm7<<<16, 256, smem_lstm>>>(Whh, bhh);
    k_nop <<<1, 32>>>();          // shift ncu slot: launch #4 = k_attn
    k_attn<<<dim3(32, 16), 128, smem_attn>>>();
    k_feat<<<4096,         256>>>(x, proto);
    for (int l = 0; l < 4; l++)
        k_mlp<<<512, 256, smem_mlp>>>(Wc, bc, l);
    k_head<<<4096, 256>>>(Wh, bh, out);
}

// round 16
// speedup vs baseline: 1.1983x; 1.1429x over previous
#include <cuda_runtime.h>
#include <cuda_fp16.h>
#include <math.h>
#include <stdint.h>

typedef unsigned long long u64;

// ---------------- scratch (device globals; no allocation allowed) ----------
__device__ float g_xg  [16u*2048u*512u];   // precomputed input gates [B,S,4H]
__device__ float g_lstm[16u*2048u*128u];   // lstm hidden states [B,S,H]
__device__ float g_ctx [16u*2048u*128u];   // attention context [B,S,H]
__device__ float g_ha  [32768u*132u];      // MLP ping buffer (stride 132)
__device__ float g_hb  [32768u*132u];      // MLP pong buffer

__device__ __forceinline__ float sigf(float x) {
    return __fdividef(1.f, 1.f + __expf(-x));
}
__device__ __forceinline__ float tanh_fast(float x) {
    return fmaf(2.f, sigf(2.f * x), -1.f);
}

// packed f32x2 helpers ------------------------------------------------------
__device__ __forceinline__ void fma2(u64& c, u64 a, u64 b) {
    asm("fma.rn.f32x2 %0, %1, %2, %0;" : "+l"(c) : "l"(a), "l"(b));
}
__device__ __forceinline__ float2 upk(u64 v) {
    unsigned lo, hi;
    asm("mov.b64 {%0, %1}, %2;" : "=r"(lo), "=r"(hi) : "l"(v));
    return make_float2(__uint_as_float(lo), __uint_as_float(hi));
}
__device__ __forceinline__ float hsum2(u64 v) { float2 f = upk(v); return f.x + f.y; }
__device__ __forceinline__ unsigned f2h2(float x, float y) {
    __half2 h = __floats2half2_rn(x, y);
    return *(unsigned*)&h;
}
// half2 fma: acc += a*b (fp16 math)
__device__ __forceinline__ void hfma2(unsigned& acc, unsigned a, unsigned b) {
    asm("fma.rn.f16x2 %0, %1, %2, %0;" : "+r"(acc) : "r"(a), "r"(b));
}
__device__ __forceinline__ float hsumh2(unsigned h2bits) {
    __half2 h = *(__half2*)&h2bits;
    float2 f = __half22float2(h);
    return f.x + f.y;
}

// tf32 helpers ---------------------------------------------------------------
__device__ __forceinline__ unsigned tf32of(float f) {
    unsigned u; asm("cvt.rna.tf32.f32 %0, %1;" : "=r"(u) : "f"(f)); return u;
}
__device__ __forceinline__ void mma_tf32(float* c, const unsigned* a,
                                         unsigned b0, unsigned b1) {
    asm volatile(
        "mma.sync.aligned.m16n8k8.row.col.f32.tf32.tf32.f32 "
        "{%0,%1,%2,%3}, {%4,%5,%6,%7}, {%8,%9}, {%0,%1,%2,%3};"
        : "+f"(c[0]), "+f"(c[1]), "+f"(c[2]), "+f"(c[3])
        : "r"(a[0]), "r"(a[1]), "r"(a[2]), "r"(a[3]), "r"(b0), "r"(b1));
}

__global__ void k_nop() {}

// ---------------- K1: xg = x @ W_ih^T + b_ih — PROVEN f32x2 (R4) ----------
__global__ void k_xg(const float* __restrict__ x,
                     const float* __restrict__ Wih,
                     const float* __restrict__ bih) {
    extern __shared__ float sm[];
    float* xs = sm;            // [64][132]
    float* ws = sm + 64 * 132; // [64][132]
    const int m0 = blockIdx.x * 64;
    const int g0 = blockIdx.y * 64;
    const int tid = threadIdx.x;

    for (int i = tid; i < 64 * 132; i += 256) {
        int r = i / 132, c = i - r * 132;
        xs[i] = (c < 129) ? x[(size_t)(m0 + r) * 129 + c] : 0.f;
    }
    for (int i = tid; i < 64 * 132; i += 256) {
        int r = i / 132, c = i - r * 132;
        ws[i] = (c < 129) ? Wih[(size_t)(g0 + r) * 129 + c] : 0.f;
    }
    __syncthreads();

    const int ty = tid >> 4, tx = tid & 15;
    u64 acc2[4][4] = {};
    const ulonglong2* xs2 = (const ulonglong2*)xs;
    const ulonglong2* ws2 = (const ulonglong2*)ws;

#pragma unroll 3
    for (int k = 0; k < 33; k++) {
        ulonglong2 xv[4], wv[4];
#pragma unroll
        for (int i = 0; i < 4; i++) xv[i] = xs2[(4 * ty + i) * 33 + k];
#pragma unroll
        for (int j = 0; j < 4; j++) wv[j] = ws2[(4 * tx + j) * 33 + k];
#pragma unroll
        for (int i = 0; i < 4; i++)
#pragma unroll
            for (int j = 0; j < 4; j++) {
                fma2(acc2[i][j], xv[i].x, wv[j].x);
                fma2(acc2[i][j], xv[i].y, wv[j].y);
            }
    }

#pragma unroll
    for (int i = 0; i < 4; i++)
#pragma unroll
        for (int j = 0; j < 4; j++) {
            int g = g0 + 4 * tx + j;
            g_xg[(size_t)(m0 + 4 * ty + i) * 512 + g] = hsum2(acc2[i][j]) + bih[g];
        }
}

// ---------------- K2: LSTM — all-register fp16 weights, HFMA2 dot ----------
// 16 CTAs, 512 threads, 1 gate/thread (gt=t&3: i,f,g,o; dim jd=t>>2).
// 128 weights live as 64 half2 registers. h double-buffered in smem as fp16.
// Dot via 4 parallel half2 chains; cell state / activations fp32.
__global__ void __launch_bounds__(512, 1)
k_lstm9(const float* __restrict__ Whh, const float* __restrict__ bhh) {
    __shared__ __half hb[2][128];

    const int t  = threadIdx.x;
    const int gt = t & 3;                 // 0=i,1=f,2=g,3=o
    const int jd = t >> 2;                // 0..127
    const int b  = blockIdx.x;
    const int row = gt * 128 + jd;

    // load 128 fp32 weights, convert to 64 half2 regs
    unsigned wh[64];
    {
        const float4* Wp = (const float4*)(Whh + (size_t)row * 128);
#pragma unroll
        for (int k = 0; k < 32; k++) {
            float4 v = Wp[k];
            wh[2 * k]     = f2h2(v.x, v.y);
            wh[2 * k + 1] = f2h2(v.z, v.w);
        }
    }
    const float bg = bhh[row];

    if (t < 128) hb[0][t] = __float2half(0.f);
    float c = 0.f;

    const float* xgp = g_xg + (size_t)b * 2048 * 512 + row;
    float xgv = xgp[0];
    __syncthreads();

    const int lane = t & 31;
    const int qb   = lane & ~3;
    const bool leader = (gt == 0);
    float* glout = g_lstm + (size_t)b * 2048 * 128 + jd;

    for (int s = 0; s < 2048; s++) {
        float nx = (s + 1 < 2048) ? xgp[(size_t)(s + 1) * 512] : 0.f;

        // dot(w, h) in fp16: 16 x LDS.128 (8 halves each), 64 HFMA2
        const uint4* h4 = (const uint4*)hb[s & 1];
        unsigned a0 = 0u, a1 = 0u, a2 = 0u, a3 = 0u;
#pragma unroll
        for (int k = 0; k < 16; k++) {
            uint4 hv = h4[k];
            hfma2(a0, wh[4 * k],     hv.x);
            hfma2(a1, wh[4 * k + 1], hv.y);
            hfma2(a2, wh[4 * k + 2], hv.z);
            hfma2(a3, wh[4 * k + 3], hv.w);
        }
        float pre = hsumh2(a0) + hsumh2(a1) + hsumh2(a2) + hsumh2(a3) + xgv + bg;

        // per-lane activation, quad shfl combine
        float act = (gt == 2) ? tanh_fast(pre) : sigf(pre);
        float fa = __shfl_sync(0xffffffffu, act, qb + 1, 32);
        float ga = __shfl_sync(0xffffffffu, act, qb + 2, 32);
        float oa = __shfl_sync(0xffffffffu, act, qb + 3, 32);

        if (leader) {
            c = fmaf(fa, c, act * ga);        // act = sig(i)
            float h = oa * tanh_fast(c);
            glout[(size_t)s * 128] = h;
            hb[(s + 1) & 1][jd] = __float2half_rn(h);
        }
        xgv = nx;
        __syncthreads();
    }
}

// ---------------- K3: flash attention, tf32 mma, Q-fragments in regs (R14) -
__global__ void __launch_bounds__(128) k_attn() {
    extern __shared__ float sm[];
    float* ks = sm;                 // [64][132]: q tile during init, then K/V
    float* ps = sm + 64 * 132;      // [64][68]  tf32 probs

    const int b  = blockIdx.y;
    const int r0 = blockIdx.x * 64;
    const float* base = g_lstm + (size_t)b * 2048 * 128;
    const int tid  = threadIdx.x;
    const int warp = tid >> 5, lane = tid & 31;
    const int gid  = lane >> 2, tig = lane & 3;
    const int wr   = warp * 16;
    const float rs = 0.08804509063256238f; // 1/sqrt(129)

    {   // stage q tile into ks: scale + tf32-round
        const float4* qg = (const float4*)(base + (size_t)r0 * 128);
        float4* ks4 = (float4*)ks;
        for (int i = tid; i < 2048; i += 128) {
            int row = i >> 5, c = i & 31;
            float4 v = qg[row * 32 + c];
            v.x = __uint_as_float(tf32of(v.x * rs));
            v.y = __uint_as_float(tf32of(v.y * rs));
            v.z = __uint_as_float(tf32of(v.z * rs));
            v.w = __uint_as_float(tf32of(v.w * rs));
            ks4[row * 33 + c] = v;
        }
    }
    __syncthreads();

    // load Q fragments into registers (64 regs)
    unsigned qf[16][4];
    {
        const unsigned* ksu0 = (const unsigned*)ks;
#pragma unroll
        for (int kk = 0; kk < 16; kk++) {
            int cc = kk * 8 + tig;
            qf[kk][0] = ksu0[(wr + gid)     * 132 + cc];
            qf[kk][1] = ksu0[(wr + gid + 8) * 132 + cc];
            qf[kk][2] = ksu0[(wr + gid)     * 132 + cc + 4];
            qf[kk][3] = ksu0[(wr + gid + 8) * 132 + cc + 4];
        }
    }

    float m0 = -1e30f, m1 = -1e30f, l0 = 0.f, l1 = 0.f;
    float o[16][4];
#pragma unroll
    for (int n = 0; n < 16; n++) { o[n][0]=0.f; o[n][1]=0.f; o[n][2]=0.f; o[n][3]=0.f; }

    const unsigned* ksu = (const unsigned*)ks;

    for (int kt = 0; kt < 32; kt++) {
        __syncthreads();   // protects qf reads (iter 0) / prior phase-2 reads
        {   // stage K/V chunk as tf32
            const float4* kg = (const float4*)(base + (size_t)kt * 64 * 128);
            float4* ks4 = (float4*)ks;
            for (int i = tid; i < 2048; i += 128) {
                int row = i >> 5, c = i & 31;
                float4 v = kg[row * 32 + c];
                v.x = __uint_as_float(tf32of(v.x));
                v.y = __uint_as_float(tf32of(v.y));
                v.z = __uint_as_float(tf32of(v.z));
                v.w = __uint_as_float(tf32of(v.w));
                ks4[row * 33 + c] = v;
            }
        }
        __syncthreads();

        // phase 1: S(16x64) = Q @ K^T  (A from registers)
        float s[8][4];
#pragma unroll
        for (int n = 0; n < 8; n++) { s[n][0]=0.f; s[n][1]=0.f; s[n][2]=0.f; s[n][3]=0.f; }
#pragma unroll
        for (int kk = 0; kk < 16; kk++) {
            int cc = kk * 8 + tig;
#pragma unroll
            for (int n = 0; n < 8; n++) {
                unsigned b0 = ksu[(n * 8 + gid) * 132 + cc];
                unsigned b1 = ksu[(n * 8 + gid) * 132 + cc + 4];
                mma_tf32(s[n], qf[kk], b0, b1);
            }
        }

        // online softmax
        float vm0 = -1e30f, vm1 = -1e30f;
#pragma unroll
        for (int n = 0; n < 8; n++) {
            vm0 = fmaxf(vm0, fmaxf(s[n][0], s[n][1]));
            vm1 = fmaxf(vm1, fmaxf(s[n][2], s[n][3]));
        }
        vm0 = fmaxf(vm0, __shfl_xor_sync(0xffffffffu, vm0, 1));
        vm0 = fmaxf(vm0, __shfl_xor_sync(0xffffffffu, vm0, 2));
        vm1 = fmaxf(vm1, __shfl_xor_sync(0xffffffffu, vm1, 1));
        vm1 = fmaxf(vm1, __shfl_xor_sync(0xffffffffu, vm1, 2));
        float nm0 = fmaxf(m0, vm0), nm1 = fmaxf(m1, vm1);

        float sum0 = 0.f, sum1 = 0.f;
#pragma unroll
        for (int n = 0; n < 8; n++) {
            float p0 = __expf(s[n][0] - nm0);
            float p1 = __expf(s[n][1] - nm0);
            float p2 = __expf(s[n][2] - nm1);
            float p3 = __expf(s[n][3] - nm1);
            sum0 += p0 + p1; sum1 += p2 + p3;
            float* pp = ps + (wr + gid) * 68 + n * 8 + 2 * tig;
            pp[0] = __uint_as_float(tf32of(p0));
            pp[1] = __uint_as_float(tf32of(p1));
            float* pq = ps + (wr + gid + 8) * 68 + n * 8 + 2 * tig;
            pq[0] = __uint_as_float(tf32of(p2));
            pq[1] = __uint_as_float(tf32of(p3));
        }
        sum0 += __shfl_xor_sync(0xffffffffu, sum0, 1);
        sum0 += __shfl_xor_sync(0xffffffffu, sum0, 2);
        sum1 += __shfl_xor_sync(0xffffffffu, sum1, 1);
        sum1 += __shfl_xor_sync(0xffffffffu, sum1, 2);
        float alpha0 = __expf(m0 - nm0), alpha1 = __expf(m1 - nm1);
        l0 = l0 * alpha0 + sum0; m0 = nm0;
        l1 = l1 * alpha1 + sum1; m1 = nm1;
        __syncwarp();   // ps written/read within the same warp only

        // phase 2: O(16x128) += P @ V
#pragma unroll
        for (int n = 0; n < 16; n++) {
            o[n][0] *= alpha0; o[n][1] *= alpha0;
            o[n][2] *= alpha1; o[n][3] *= alpha1;
        }
        const unsigned* psu = (const unsigned*)ps;
#pragma unroll
        for (int kk = 0; kk < 8; kk++) {
            unsigned pa[4];
            pa[0] = psu[(wr + gid)     * 68 + kk * 8 + tig];
            pa[1] = psu[(wr + gid + 8) * 68 + kk * 8 + tig];
            pa[2] = psu[(wr + gid)     * 68 + kk * 8 + tig + 4];
            pa[3] = psu[(wr + gid + 8) * 68 + kk * 8 + tig + 4];
#pragma unroll
            for (int n = 0; n < 16; n++) {
                unsigned b0 = ksu[(kk * 8 + tig)     * 132 + n * 8 + gid];
                unsigned b1 = ksu[(kk * 8 + tig + 4) * 132 + n * 8 + gid];
                mma_tf32(o[n], pa, b0, b1);
            }
        }
    }

    // epilogue
    float inv0 = 1.f / l0, inv1 = 1.f / l1;
    int row0 = r0 + wr + gid, row1 = row0 + 8;
    float* d0 = g_ctx + ((size_t)b * 2048 + row0) * 128;
    float* d1 = g_ctx + ((size_t)b * 2048 + row1) * 128;
#pragma unroll
    for (int n = 0; n < 16; n++) {
        int cc = n * 8 + 2 * tig;
        *(float2*)(d0 + cc) = make_float2(o[n][0] * inv0, o[n][1] * inv0);
        *(float2*)(d1 + cc) = make_float2(o[n][2] * inv1, o[n][3] * inv1);
    }
}

// ---------------- K4: concat(context, RBF kernel feature), pad to 132 ------
__global__ void k_feat(const float* __restrict__ x, const float* __restrict__ pr) {
    const int tid = threadIdx.x;
    const int warp = tid >> 5, lane = tid & 31;
    const size_t mrow = (size_t)blockIdx.x * 8 + warp;

    const float4* c4 = (const float4*)(g_ctx + mrow * 128);
    float4* o4 = (float4*)(g_ha + mrow * 132);
    o4[lane] = c4[lane];

    const float* xr = x  + mrow * 129;
    const float* pp = pr + mrow * 129;
    float ss = 0.f;
    for (int j2 = lane; j2 < 129; j2 += 32) {
        float d = xr[j2] - pp[j2];
        ss += d * d;
    }
#pragma unroll
    for (int dd = 16; dd; dd >>= 1) ss += __shfl_xor_sync(0xffffffffu, ss, dd);
    if (lane == 0)      g_ha[mrow * 132 + 128] = __expf(-ss);
    else if (lane < 4)  g_ha[mrow * 132 + 128 + lane] = 0.f;
}

// ---------------- K5: one MLP layer h = relu(h @ Wc[l]^T + bc[l]) — PROVEN -
__global__ void k_mlp(const float* __restrict__ Wc, const float* __restrict__ bc, int l) {
    extern __shared__ float sm[];
    float* Wsh  = sm;              // [132][134]
    float* insh = sm + 132 * 134;  // [64][132]
    const float* in  = (l & 1) ? g_hb : g_ha;
    float*       out = (l & 1) ? g_ha : g_hb;

    const int m0 = blockIdx.x * 64;
    const int tid = threadIdx.x;
    const float* W  = Wc + (size_t)l * 129 * 129;
    const float* bb = bc + (size_t)l * 129;

    for (int i = tid; i < 132 * 134; i += 256) {
        int r = i / 134, c = i - r * 134;
        Wsh[i] = (r < 129 && c < 129) ? W[r * 129 + c] : 0.f;
    }
    for (int i = tid; i < 64 * 132; i += 256)
        insh[i] = in[(size_t)m0 * 132 + i];
    __syncthreads();

    const int warp = tid >> 5, lane = tid & 31;
    const int rb = warp * 8;
    const u64* W2 = (const u64*)Wsh;   // row stride 67 pairs

#pragma unroll
    for (int q = 0; q < 2; q++) {
        u64 acc2[4][5] = {};
        const int r0 = rb + 4 * q;
        const u64* h0p = (const u64*)(insh + (r0 + 0) * 132);
        const u64* h1p = (const u64*)(insh + (r0 + 1) * 132);
        const u64* h2p = (const u64*)(insh + (r0 + 2) * 132);
        const u64* h3p = (const u64*)(insh + (r0 + 3) * 132);
#pragma unroll 2
        for (int jp = 0; jp < 66; jp++) {
            u64 h0 = h0p[jp], h1 = h1p[jp], h2 = h2p[jp], h3 = h3p[jp];
#pragma unroll
            for (int cg = 0; cg < 5; cg++) {
                int cc = lane + 32 * cg;
                if (cc < 132) {
                    u64 w = W2[cc * 67 + jp];
                    fma2(acc2[0][cg], h0, w); fma2(acc2[1][cg], h1, w);
                    fma2(acc2[2][cg], h2, w); fma2(acc2[3][cg], h3, w);
                }
            }
        }
#pragma unroll
        for (int cg = 0; cg < 5; cg++) {
            int cc = lane + 32 * cg;
            if (cc < 132) {
                float bv = (cc < 129) ? bb[cc] : 0.f;
#pragma unroll
                for (int i = 0; i < 4; i++)
                    out[(size_t)(m0 + rb + 4 * q + i) * 132 + cc] =
                        fmaxf(hsum2(acc2[i][cg]) + bv, 0.f);
            }
        }
    }
}

// ---------------- K6: head + log_softmax -----------------------------------
__global__ void k_head(const float* __restrict__ Wh, const float* __restrict__ bh,
                       float* __restrict__ out) {
    const int tid = threadIdx.x;
    const int warp = tid >> 5, lane = tid & 31;
    const size_t mrow = (size_t)blockIdx.x * 8 + warp;
    const float* hr = g_ha + mrow * 132;

    float s0 = 0.f, s1 = 0.f;
    for (int j2 = lane; j2 < 129; j2 += 32) {
        float hv = hr[j2];
        s0 += hv * Wh[j2];
        s1 += hv * Wh[129 + j2];
    }
#pragma unroll
    for (int dd = 16; dd; dd >>= 1) {
        s0 += __shfl_xor_sync(0xffffffffu, s0, dd);
        s1 += __shfl_xor_sync(0xffffffffu, s1, dd);
    }
    if (lane == 0) {
        s0 += bh[0]; s1 += bh[1];
        float mx = fmaxf(s0, s1);
        float lse = mx + logf(__expf(s0 - mx) + __expf(s1 - mx));
        out[2 * mrow]     = s0 - lse;
        out[2 * mrow + 1] = s1 - lse;
    }
}

// ---------------- launch ---------------------------------------------------
extern "C" void kernel_launch(void* const* d_in, const int* in_sizes, int n_in,
                              void* d_out, int out_size) {
    const float* x     = (const float*)d_in[0];
    const float* proto = (const float*)d_in[1];
    const float* Wih   = (const float*)d_in[2];
    const float* Whh   = (const float*)d_in[3];
    const float* bih   = (const float*)d_in[4];
    const float* bhh   = (const float*)d_in[5];
    const float* Wc    = (const float*)d_in[6];
    const float* bc    = (const float*)d_in[7];
    const float* Wh    = (const float*)d_in[8];
    const float* bh    = (const float*)d_in[9];
    float* out = (float*)d_out;

    const int smem_xg   = 2 * 64 * 132 * 4;                 // 67584
    const int smem_attn = (64 * 132 + 64 * 68) * 4;         // 51200
    const int smem_mlp  = (132 * 134 + 64 * 132) * 4;       // 104544

    cudaFuncSetAttribute(k_xg,   cudaFuncAttributeMaxDynamicSharedMemorySize, smem_xg);
    cudaFuncSetAttribute(k_attn, cudaFuncAttributeMaxDynamicSharedMemorySize, smem_attn);
    cudaFuncSetAttribute(k_mlp,  cudaFuncAttributeMaxDynamicSharedMemorySize, smem_mlp);

    k_xg  <<<dim3(512, 8), 256, smem_xg>>>(x, Wih, bih);
    k_nop <<<1, 32>>>();          // shift ncu slot:
    k_nop <<<1, 32>>>();          // ... so launch #4 is k_lstm9
    k_lstm9<<<16, 512>>>(Whh, bhh);
    k_attn<<<dim3(32, 16), 128, smem_attn>>>();
    k_feat<<<4096,         256>>>(x, proto);
    for (int l = 0; l < 4; l++)
        k_mlp<<<512, 256, smem_mlp>>>(Wc, bc, l);
    k_head<<<4096, 256>>>(Wh, bh, out);
}

// round 17
// speedup vs baseline: 1.3334x; 1.1127x over previous
#include <cuda_runtime.h>
#include <cuda_fp16.h>
#include <math.h>
#include <stdint.h>

typedef unsigned long long u64;

// ---------------- scratch (device globals; no allocation allowed) ----------
__device__ float g_xg  [16u*2048u*512u];   // precomputed input gates [B,S,4H]
__device__ float g_lstm[16u*2048u*128u];   // lstm hidden states [B,S,H]
__device__ float g_ctx [16u*2048u*128u];   // attention context [B,S,H]
__device__ float g_ha  [32768u*132u];      // MLP ping buffer (stride 132)
__device__ float g_hb  [32768u*132u];      // MLP pong buffer

__device__ __forceinline__ float sigf(float x) {
    return __fdividef(1.f, 1.f + __expf(-x));
}
__device__ __forceinline__ float tanha(float x) {      // MUFU.TANH
    float r; asm("tanh.approx.f32 %0, %1;" : "=f"(r) : "f"(x)); return r;
}
__device__ __forceinline__ float sigt(float x) {       // sigmoid via MUFU.TANH
    return fmaf(0.5f, tanha(0.5f * x), 0.5f);
}

// packed f32x2 helpers ------------------------------------------------------
__device__ __forceinline__ void fma2(u64& c, u64 a, u64 b) {
    asm("fma.rn.f32x2 %0, %1, %2, %0;" : "+l"(c) : "l"(a), "l"(b));
}
__device__ __forceinline__ float2 upk(u64 v) {
    unsigned lo, hi;
    asm("mov.b64 {%0, %1}, %2;" : "=r"(lo), "=r"(hi) : "l"(v));
    return make_float2(__uint_as_float(lo), __uint_as_float(hi));
}
__device__ __forceinline__ float hsum2(u64 v) { float2 f = upk(v); return f.x + f.y; }
__device__ __forceinline__ unsigned f2h2(float x, float y) {
    __half2 h = __floats2half2_rn(x, y);
    return *(unsigned*)&h;
}
__device__ __forceinline__ void hfma2(unsigned& acc, unsigned a, unsigned b) {
    asm("fma.rn.f16x2 %0, %1, %2, %0;" : "+r"(acc) : "r"(a), "r"(b));
}
__device__ __forceinline__ float hsumh2(unsigned h2bits) {
    __half2 h = *(__half2*)&h2bits;
    float2 f = __half22float2(h);
    return f.x + f.y;
}

// tf32 helpers ---------------------------------------------------------------
__device__ __forceinline__ unsigned tf32of(float f) {
    unsigned u; asm("cvt.rna.tf32.f32 %0, %1;" : "=r"(u) : "f"(f)); return u;
}
__device__ __forceinline__ void mma_tf32(float* c, const unsigned* a,
                                         unsigned b0, unsigned b1) {
    asm volatile(
        "mma.sync.aligned.m16n8k8.row.col.f32.tf32.tf32.f32 "
        "{%0,%1,%2,%3}, {%4,%5,%6,%7}, {%8,%9}, {%0,%1,%2,%3};"
        : "+f"(c[0]), "+f"(c[1]), "+f"(c[2]), "+f"(c[3])
        : "r"(a[0]), "r"(a[1]), "r"(a[2]), "r"(a[3]), "r"(b0), "r"(b1));
}

__global__ void k_nop() {}

// ---------------- K1: xg = x @ W_ih^T + b_ih — PROVEN f32x2 (R4) ----------
__global__ void k_xg(const float* __restrict__ x,
                     const float* __restrict__ Wih,
                     const float* __restrict__ bih) {
    extern __shared__ float sm[];
    float* xs = sm;            // [64][132]
    float* ws = sm + 64 * 132; // [64][132]
    const int m0 = blockIdx.x * 64;
    const int g0 = blockIdx.y * 64;
    const int tid = threadIdx.x;

    for (int i = tid; i < 64 * 132; i += 256) {
        int r = i / 132, c = i - r * 132;
        xs[i] = (c < 129) ? x[(size_t)(m0 + r) * 129 + c] : 0.f;
    }
    for (int i = tid; i < 64 * 132; i += 256) {
        int r = i / 132, c = i - r * 132;
        ws[i] = (c < 129) ? Wih[(size_t)(g0 + r) * 129 + c] : 0.f;
    }
    __syncthreads();

    const int ty = tid >> 4, tx = tid & 15;
    u64 acc2[4][4] = {};
    const ulonglong2* xs2 = (const ulonglong2*)xs;
    const ulonglong2* ws2 = (const ulonglong2*)ws;

#pragma unroll 3
    for (int k = 0; k < 33; k++) {
        ulonglong2 xv[4], wv[4];
#pragma unroll
        for (int i = 0; i < 4; i++) xv[i] = xs2[(4 * ty + i) * 33 + k];
#pragma unroll
        for (int j = 0; j < 4; j++) wv[j] = ws2[(4 * tx + j) * 33 + k];
#pragma unroll
        for (int i = 0; i < 4; i++)
#pragma unroll
            for (int j = 0; j < 4; j++) {
                fma2(acc2[i][j], xv[i].x, wv[j].x);
                fma2(acc2[i][j], xv[i].y, wv[j].y);
            }
    }

#pragma unroll
    for (int i = 0; i < 4; i++)
#pragma unroll
        for (int j = 0; j < 4; j++) {
            int g = g0 + 4 * tx + j;
            g_xg[(size_t)(m0 + 4 * ty + i) * 512 + g] = hsum2(acc2[i][j]) + bih[g];
        }
}

// ---------------- K2: LSTM — fp16 RF weights + MUFU.TANH activations -------
__global__ void __launch_bounds__(512, 1)
k_lstm9(const float* __restrict__ Whh, const float* __restrict__ bhh) {
    __shared__ __half hb[2][128];

    const int t  = threadIdx.x;
    const int gt = t & 3;                 // 0=i,1=f,2=g,3=o
    const int jd = t >> 2;                // 0..127
    const int b  = blockIdx.x;
    const int row = gt * 128 + jd;

    unsigned wh[64];
    {
        const float4* Wp = (const float4*)(Whh + (size_t)row * 128);
#pragma unroll
        for (int k = 0; k < 32; k++) {
            float4 v = Wp[k];
            wh[2 * k]     = f2h2(v.x, v.y);
            wh[2 * k + 1] = f2h2(v.z, v.w);
        }
    }
    const float bg = bhh[row];

    if (t < 128) hb[0][t] = __float2half(0.f);
    float c = 0.f;

    const float* xgp = g_xg + (size_t)b * 2048 * 512 + row;
    float xgv = xgp[0];
    __syncthreads();

    const int lane = t & 31;
    const int qb   = lane & ~3;
    const bool leader = (gt == 0);
    float* glout = g_lstm + (size_t)b * 2048 * 128 + jd;

    for (int s = 0; s < 2048; s++) {
        float nx = (s + 1 < 2048) ? xgp[(size_t)(s + 1) * 512] : 0.f;

        const uint4* h4 = (const uint4*)hb[s & 1];
        unsigned a0 = 0u, a1 = 0u, a2 = 0u, a3 = 0u;
#pragma unroll
        for (int k = 0; k < 16; k++) {
            uint4 hv = h4[k];
            hfma2(a0, wh[4 * k],     hv.x);
            hfma2(a1, wh[4 * k + 1], hv.y);
            hfma2(a2, wh[4 * k + 2], hv.z);
            hfma2(a3, wh[4 * k + 3], hv.w);
        }
        float pre = hsumh2(a0) + hsumh2(a1) + hsumh2(a2) + hsumh2(a3) + xgv + bg;

        // 1-MUFU activations (R10-proven precision)
        float act = (gt == 2) ? tanha(pre) : sigt(pre);
        float fa = __shfl_sync(0xffffffffu, act, qb + 1, 32);
        float ga = __shfl_sync(0xffffffffu, act, qb + 2, 32);
        float oa = __shfl_sync(0xffffffffu, act, qb + 3, 32);

        if (leader) {
            c = fmaf(fa, c, act * ga);        // act = sig(i)
            float h = oa * tanha(c);
            glout[(size_t)s * 128] = h;
            hb[(s + 1) & 1][jd] = __float2half_rn(h);
        }
        xgv = nx;
        __syncthreads();
    }
}

// ---------------- K3: flash attention, tf32 mma, Q-fragments in regs (R14) -
__global__ void __launch_bounds__(128) k_attn() {
    extern __shared__ float sm[];
    float* ks = sm;                 // [64][132]: q tile during init, then K/V
    float* ps = sm + 64 * 132;      // [64][68]  tf32 probs

    const int b  = blockIdx.y;
    const int r0 = blockIdx.x * 64;
    const float* base = g_lstm + (size_t)b * 2048 * 128;
    const int tid  = threadIdx.x;
    const int warp = tid >> 5, lane = tid & 31;
    const int gid  = lane >> 2, tig = lane & 3;
    const int wr   = warp * 16;
    const float rs = 0.08804509063256238f; // 1/sqrt(129)

    {   // stage q tile into ks: scale + tf32-round
        const float4* qg = (const float4*)(base + (size_t)r0 * 128);
        float4* ks4 = (float4*)ks;
        for (int i = tid; i < 2048; i += 128) {
            int row = i >> 5, c = i & 31;
            float4 v = qg[row * 32 + c];
            v.x = __uint_as_float(tf32of(v.x * rs));
            v.y = __uint_as_float(tf32of(v.y * rs));
            v.z = __uint_as_float(tf32of(v.z * rs));
            v.w = __uint_as_float(tf32of(v.w * rs));
            ks4[row * 33 + c] = v;
        }
    }
    __syncthreads();

    unsigned qf[16][4];
    {
        const unsigned* ksu0 = (const unsigned*)ks;
#pragma unroll
        for (int kk = 0; kk < 16; kk++) {
            int cc = kk * 8 + tig;
            qf[kk][0] = ksu0[(wr + gid)     * 132 + cc];
            qf[kk][1] = ksu0[(wr + gid + 8) * 132 + cc];
            qf[kk][2] = ksu0[(wr + gid)     * 132 + cc + 4];
            qf[kk][3] = ksu0[(wr + gid + 8) * 132 + cc + 4];
        }
    }

    float m0 = -1e30f, m1 = -1e30f, l0 = 0.f, l1 = 0.f;
    float o[16][4];
#pragma unroll
    for (int n = 0; n < 16; n++) { o[n][0]=0.f; o[n][1]=0.f; o[n][2]=0.f; o[n][3]=0.f; }

    const unsigned* ksu = (const unsigned*)ks;

    for (int kt = 0; kt < 32; kt++) {
        __syncthreads();
        {   // stage K/V chunk as tf32
            const float4* kg = (const float4*)(base + (size_t)kt * 64 * 128);
            float4* ks4 = (float4*)ks;
            for (int i = tid; i < 2048; i += 128) {
                int row = i >> 5, c = i & 31;
                float4 v = kg[row * 32 + c];
                v.x = __uint_as_float(tf32of(v.x));
                v.y = __uint_as_float(tf32of(v.y));
                v.z = __uint_as_float(tf32of(v.z));
                v.w = __uint_as_float(tf32of(v.w));
                ks4[row * 33 + c] = v;
            }
        }
        __syncthreads();

        float s[8][4];
#pragma unroll
        for (int n = 0; n < 8; n++) { s[n][0]=0.f; s[n][1]=0.f; s[n][2]=0.f; s[n][3]=0.f; }
#pragma unroll
        for (int kk = 0; kk < 16; kk++) {
            int cc = kk * 8 + tig;
#pragma unroll
            for (int n = 0; n < 8; n++) {
                unsigned b0 = ksu[(n * 8 + gid) * 132 + cc];
                unsigned b1 = ksu[(n * 8 + gid) * 132 + cc + 4];
                mma_tf32(s[n], qf[kk], b0, b1);
            }
        }

        float vm0 = -1e30f, vm1 = -1e30f;
#pragma unroll
        for (int n = 0; n < 8; n++) {
            vm0 = fmaxf(vm0, fmaxf(s[n][0], s[n][1]));
            vm1 = fmaxf(vm1, fmaxf(s[n][2], s[n][3]));
        }
        vm0 = fmaxf(vm0, __shfl_xor_sync(0xffffffffu, vm0, 1));
        vm0 = fmaxf(vm0, __shfl_xor_sync(0xffffffffu, vm0, 2));
        vm1 = fmaxf(vm1, __shfl_xor_sync(0xffffffffu, vm1, 1));
        vm1 = fmaxf(vm1, __shfl_xor_sync(0xffffffffu, vm1, 2));
        float nm0 = fmaxf(m0, vm0), nm1 = fmaxf(m1, vm1);

        float sum0 = 0.f, sum1 = 0.f;
#pragma unroll
        for (int n = 0; n < 8; n++) {
            float p0 = __expf(s[n][0] - nm0);
            float p1 = __expf(s[n][1] - nm0);
            float p2 = __expf(s[n][2] - nm1);
            float p3 = __expf(s[n][3] - nm1);
            sum0 += p0 + p1; sum1 += p2 + p3;
            float* pp = ps + (wr + gid) * 68 + n * 8 + 2 * tig;
            pp[0] = __uint_as_float(tf32of(p0));
            pp[1] = __uint_as_float(tf32of(p1));
            float* pq = ps + (wr + gid + 8) * 68 + n * 8 + 2 * tig;
            pq[0] = __uint_as_float(tf32of(p2));
            pq[1] = __uint_as_float(tf32of(p3));
        }
        sum0 += __shfl_xor_sync(0xffffffffu, sum0, 1);
        sum0 += __shfl_xor_sync(0xffffffffu, sum0, 2);
        sum1 += __shfl_xor_sync(0xffffffffu, sum1, 1);
        sum1 += __shfl_xor_sync(0xffffffffu, sum1, 2);
        float alpha0 = __expf(m0 - nm0), alpha1 = __expf(m1 - nm1);
        l0 = l0 * alpha0 + sum0; m0 = nm0;
        l1 = l1 * alpha1 + sum1; m1 = nm1;
        __syncwarp();

#pragma unroll
        for (int n = 0; n < 16; n++) {
            o[n][0] *= alpha0; o[n][1] *= alpha0;
            o[n][2] *= alpha1; o[n][3] *= alpha1;
        }
        const unsigned* psu = (const unsigned*)ps;
#pragma unroll
        for (int kk = 0; kk < 8; kk++) {
            unsigned pa[4];
            pa[0] = psu[(wr + gid)     * 68 + kk * 8 + tig];
            pa[1] = psu[(wr + gid + 8) * 68 + kk * 8 + tig];
            pa[2] = psu[(wr + gid)     * 68 + kk * 8 + tig + 4];
            pa[3] = psu[(wr + gid + 8) * 68 + kk * 8 + tig + 4];
#pragma unroll
            for (int n = 0; n < 16; n++) {
                unsigned b0 = ksu[(kk * 8 + tig)     * 132 + n * 8 + gid];
                unsigned b1 = ksu[(kk * 8 + tig + 4) * 132 + n * 8 + gid];
                mma_tf32(o[n], pa, b0, b1);
            }
        }
    }

    float inv0 = 1.f / l0, inv1 = 1.f / l1;
    int row0 = r0 + wr + gid, row1 = row0 + 8;
    float* d0 = g_ctx + ((size_t)b * 2048 + row0) * 128;
    float* d1 = g_ctx + ((size_t)b * 2048 + row1) * 128;
#pragma unroll
    for (int n = 0; n < 16; n++) {
        int cc = n * 8 + 2 * tig;
        *(float2*)(d0 + cc) = make_float2(o[n][0] * inv0, o[n][1] * inv0);
        *(float2*)(d1 + cc) = make_float2(o[n][2] * inv1, o[n][3] * inv1);
    }
}

// ---------------- K4: concat(context, RBF kernel feature), pad to 132 ------
__global__ void k_feat(const float* __restrict__ x, const float* __restrict__ pr) {
    const int tid = threadIdx.x;
    const int warp = tid >> 5, lane = tid & 31;
    const size_t mrow = (size_t)blockIdx.x * 8 + warp;

    const float4* c4 = (const float4*)(g_ctx + mrow * 128);
    float4* o4 = (float4*)(g_ha + mrow * 132);
    o4[lane] = c4[lane];

    const float* xr = x  + mrow * 129;
    const float* pp = pr + mrow * 129;
    float ss = 0.f;
    for (int j2 = lane; j2 < 129; j2 += 32) {
        float d = xr[j2] - pp[j2];
        ss += d * d;
    }
#pragma unroll
    for (int dd = 16; dd; dd >>= 1) ss += __shfl_xor_sync(0xffffffffu, ss, dd);
    if (lane == 0)      g_ha[mrow * 132 + 128] = __expf(-ss);
    else if (lane < 4)  g_ha[mrow * 132 + 128 + lane] = 0.f;
}

// ---------------- K5: MLP layer via tf32 mma (division-free staging) -------
// 256 thr = 8 warps. M=64 rows/block (grid 512). Warp (w&3) -> 16-row group,
// (w>>2) -> n-frag half (0..8 / 9..16). 16 k-frags + exact-fp32 col-128 fixup.
__global__ void __launch_bounds__(256) k_mlp_t2(const float* __restrict__ Wc,
                                                const float* __restrict__ bc, int l) {
    extern __shared__ float sm[];
    float* Wsh  = sm;               // [136][132] tf32 (col 128 exact fp32)
    float* insh = sm + 136 * 132;   // [64][132]
    const float* in  = (l & 1) ? g_hb : g_ha;
    float*       out = (l & 1) ? g_ha : g_hb;

    const int m0 = blockIdx.x * 64;
    const int tid = threadIdx.x;
    const int warp = tid >> 5, lane = tid & 31;
    const int gid  = lane >> 2, tig = lane & 3;
    const int w4 = warp & 3, nh = warp >> 2;
    const int wr = w4 * 16;
    const float* W  = Wc + (size_t)l * 129 * 129;
    const float* bb = bc + (size_t)l * 129;

    // stage W rows 0..135 (129..135 zero), cols 0..131
#pragma unroll
    for (int k = 0; k < 17; k++) {
        int r = warp + 8 * k;
#pragma unroll
        for (int j = 0; j < 5; j++) {
            int c = lane + 32 * j;
            if (c < 132) {
                float v = (r < 129 && c < 129) ? W[r * 129 + c] : 0.f;
                Wsh[r * 132 + c] = (c == 128) ? v : __uint_as_float(tf32of(v));
            }
        }
    }
    // stage input rows 0..63
#pragma unroll
    for (int k = 0; k < 8; k++) {
        int r = warp + 8 * k;
#pragma unroll
        for (int j = 0; j < 5; j++) {
            int c = lane + 32 * j;
            if (c < 132) {
                float v = in[(size_t)(m0 + r) * 132 + c];
                insh[r * 132 + c] = (c == 128) ? v : __uint_as_float(tf32of(v));
            }
        }
    }
    __syncthreads();

    const int n0 = nh * 9;
    const int nn = nh ? 8 : 9;
    float s[9][4];
#pragma unroll
    for (int n = 0; n < 9; n++) { s[n][0]=0.f; s[n][1]=0.f; s[n][2]=0.f; s[n][3]=0.f; }

    const unsigned* inu = (const unsigned*)insh;
    const unsigned* Wu  = (const unsigned*)Wsh;
#pragma unroll
    for (int kk = 0; kk < 16; kk++) {
        int cc = kk * 8 + tig;
        unsigned a[4];
        a[0] = inu[(wr + gid)     * 132 + cc];
        a[1] = inu[(wr + gid + 8) * 132 + cc];
        a[2] = inu[(wr + gid)     * 132 + cc + 4];
        a[3] = inu[(wr + gid + 8) * 132 + cc + 4];
        for (int n = 0; n < nn; n++) {
            int rowb = (n0 + n) * 8 + gid;
            mma_tf32(s[n], a, Wu[rowb * 132 + cc], Wu[rowb * 132 + cc + 4]);
        }
    }

    // exact fp32 fixup for k = 128
    float x0 = insh[(wr + gid)     * 132 + 128];
    float x1 = insh[(wr + gid + 8) * 132 + 128];
    for (int n = 0; n < nn; n++) {
        int col = (n0 + n) * 8 + 2 * tig;
        float w0 = Wsh[col * 132 + 128];
        float w1 = Wsh[(col + 1) * 132 + 128];
        s[n][0] += x0 * w0; s[n][1] += x0 * w1;
        s[n][2] += x1 * w0; s[n][3] += x1 * w1;
    }

    int r0 = m0 + wr + gid, r1 = r0 + 8;
    for (int n = 0; n < nn; n++) {
        int col = (n0 + n) * 8 + 2 * tig;
        if (col < 132) {
            float b0 = (col     < 129) ? bb[col]     : 0.f;
            float b1 = (col + 1 < 129) ? bb[col + 1] : 0.f;
            *(float2*)(out + (size_t)r0 * 132 + col) =
                make_float2(fmaxf(s[n][0] + b0, 0.f), fmaxf(s[n][1] + b1, 0.f));
            *(float2*)(out + (size_t)r1 * 132 + col) =
                make_float2(fmaxf(s[n][2] + b0, 0.f), fmaxf(s[n][3] + b1, 0.f));
        }
    }
}

// ---------------- K6: head + log_softmax -----------------------------------
__global__ void k_head(const float* __restrict__ Wh, const float* __restrict__ bh,
                       float* __restrict__ out) {
    const int tid = threadIdx.x;
    const int warp = tid >> 5, lane = tid & 31;
    const size_t mrow = (size_t)blockIdx.x * 8 + warp;
    const float* hr = g_ha + mrow * 132;

    float s0 = 0.f, s1 = 0.f;
    for (int j2 = lane; j2 < 129; j2 += 32) {
        float hv = hr[j2];
        s0 += hv * Wh[j2];
        s1 += hv * Wh[129 + j2];
    }
#pragma unroll
    for (int dd = 16; dd; dd >>= 1) {
        s0 += __shfl_xor_sync(0xffffffffu, s0, dd);
        s1 += __shfl_xor_sync(0xffffffffu, s1, dd);
    }
    if (lane == 0) {
        s0 += bh[0]; s1 += bh[1];
        float mx = fmaxf(s0, s1);
        float lse = mx + logf(__expf(s0 - mx) + __expf(s1 - mx));
        out[2 * mrow]     = s0 - lse;
        out[2 * mrow + 1] = s1 - lse;
    }
}

// ---------------- launch ---------------------------------------------------
extern "C" void kernel_launch(void* const* d_in, const int* in_sizes, int n_in,
                              void* d_out, int out_size) {
    const float* x     = (const float*)d_in[0];
    const float* proto = (const float*)d_in[1];
    const float* Wih   = (const float*)d_in[2];
    const float* Whh   = (const float*)d_in[3];
    const float* bih   = (const float*)d_in[4];
    const float* bhh   = (const float*)d_in[5];
    const float* Wc    = (const float*)d_in[6];
    const float* bc    = (const float*)d_in[7];
    const float* Wh    = (const float*)d_in[8];
    const float* bh    = (const float*)d_in[9];
    float* out = (float*)d_out;

    const int smem_xg   = 2 * 64 * 132 * 4;                 // 67584
    const int smem_attn = (64 * 132 + 64 * 68) * 4;         // 51200
    const int smem_mlp  = (136 * 132 + 64 * 132) * 4;       // 105600

    cudaFuncSetAttribute(k_xg,     cudaFuncAttributeMaxDynamicSharedMemorySize, smem_xg);
    cudaFuncSetAttribute(k_attn,   cudaFuncAttributeMaxDynamicSharedMemorySize, smem_attn);
    cudaFuncSetAttribute(k_mlp_t2, cudaFuncAttributeMaxDynamicSharedMemorySize, smem_mlp);

    k_xg  <<<dim3(512, 8), 256, smem_xg>>>(x, Wih, bih);
    k_nop <<<1, 32>>>();          // shift ncu slot:
    k_nop <<<1, 32>>>();          // ... so launch #4 is k_lstm9
    k_lstm9<<<16, 512>>>(Whh, bhh);
    k_attn<<<dim3(32, 16), 128, smem_attn>>>();
    k_feat<<<4096,         256>>>(x, proto);
    for (int l = 0; l < 4; l++)
        k_mlp_t2<<<512, 256, smem_mlp>>>(Wc, bc, l);
    k_head<<<4096, 256>>>(Wh, bh, out);
}